// round 3
// baseline (speedup 1.0000x reference)
#include <cuda_runtime.h>

// Problem constants (known shapes)
#define NN    50000
#define EEMAX 1600000
#define ETOT  (EEMAX + NN)
#define HID   32

// ---- static scratch (no allocation allowed) ----
__device__ int   g_deg[NN];
__device__ int   g_roff[NN + 1];
__device__ int   g_cur[NN];
__device__ int   g_csr[ETOT];
__device__ float g_lin[NN * HID];   // h = X @ W for current layer
__device__ float g_es[NN];
__device__ float g_ed[NN];
__device__ float g_t1[NN * HID];    // layer-1 aggregated output
__device__ float g_t2[NN * HID];    // layer-2 aggregated output

// ---------------- CSR build ----------------
__global__ void k_init_deg(int n) {
    int i = blockIdx.x * blockDim.x + threadIdx.x;
    if (i < n) g_deg[i] = 1;  // self loop pre-counted
}

template <typename IT>
__global__ void k_hist(const IT* __restrict__ dst, int E, int n) {
    int e = blockIdx.x * blockDim.x + threadIdx.x;
    if (e < E) {
        int d = (int)dst[e];
        if ((unsigned)d < (unsigned)n) atomicAdd(&g_deg[d], 1);
    }
}

// single-block scan over n<=50000 ints (exclusive), also fills cursor copy
__global__ void k_scan(int n) {
    __shared__ int wsum[32];
    __shared__ int carry;
    int tid = threadIdx.x, lane = tid & 31, wid = tid >> 5;
    if (tid == 0) carry = 0;
    __syncthreads();
    for (int base = 0; base < n; base += 1024) {
        int i = base + tid;
        int v = (i < n) ? g_deg[i] : 0;
        int x = v;
        #pragma unroll
        for (int o = 1; o < 32; o <<= 1) {
            int y = __shfl_up_sync(0xffffffffu, x, o);
            if (lane >= o) x += y;
        }
        if (lane == 31) wsum[wid] = x;
        __syncthreads();
        if (wid == 0) {
            int s = wsum[lane];
            #pragma unroll
            for (int o = 1; o < 32; o <<= 1) {
                int y = __shfl_up_sync(0xffffffffu, s, o);
                if (lane >= o) s += y;
            }
            wsum[lane] = s;
        }
        __syncthreads();
        int incl = x + (wid ? wsum[wid - 1] : 0) + carry;
        if (i < n) { g_roff[i] = incl - v; g_cur[i] = incl - v; }
        if (i == n - 1) g_roff[n] = incl;
        __syncthreads();
        if (tid == 1023) carry = incl;
        __syncthreads();
    }
}

template <typename IT>
__global__ void k_scatter(const IT* __restrict__ src,
                          const IT* __restrict__ dst, int E, int n) {
    int e = blockIdx.x * blockDim.x + threadIdx.x;
    int s, d;
    if (e < E) { s = (int)src[e]; d = (int)dst[e]; }
    else if (e < E + n) { s = e - E; d = s; }
    else return;
    if ((unsigned)s >= (unsigned)n || (unsigned)d >= (unsigned)n) return;
    int pos = atomicAdd(&g_cur[d], 1);
    g_csr[pos] = s;
}

// ---------------- per-layer linear + attention coefficients ----------------
template <int IN_DIM>
__global__ void k_lin(const float* __restrict__ xext, int in_sel,
                      const float* __restrict__ W,
                      const float* __restrict__ a_s,
                      const float* __restrict__ a_d, int n) {
    __shared__ float Wsh[IN_DIM * HID];
    __shared__ float ash[HID], adh[HID];
    for (int i = threadIdx.x; i < IN_DIM * HID; i += blockDim.x) Wsh[i] = W[i];
    if (threadIdx.x < HID) {
        ash[threadIdx.x] = a_s[threadIdx.x];
        adh[threadIdx.x] = a_d[threadIdx.x];
    }
    __syncthreads();
    int gw = (blockIdx.x * blockDim.x + threadIdx.x) >> 5;
    int lane = threadIdx.x & 31;
    if (gw >= n) return;
    const float* X = in_sel ? g_t1 : xext;
    const float* xr = X + (size_t)gw * IN_DIM;
    float acc = 0.f;
    #pragma unroll
    for (int k = 0; k < IN_DIM; k++)
        acc = fmaf(xr[k], Wsh[k * HID + lane], acc);
    g_lin[(size_t)gw * HID + lane] = acc;
    float es = acc * ash[lane], ed = acc * adh[lane];
    #pragma unroll
    for (int o = 16; o; o >>= 1) {
        es += __shfl_xor_sync(0xffffffffu, es, o);
        ed += __shfl_xor_sync(0xffffffffu, ed, o);
    }
    if (lane == 0) { g_es[gw] = es; g_ed[gw] = ed; }
}

// ---------------- warp-per-dst softmax aggregation (ReLU + bias fused) ----------------
__global__ void k_agg(const float* __restrict__ bias, int out_sel, int n) {
    __shared__ float bsh[HID];
    if (threadIdx.x < HID) bsh[threadIdx.x] = bias[threadIdx.x];
    __syncthreads();
    int gw = (blockIdx.x * blockDim.x + threadIdx.x) >> 5;
    int lane = threadIdx.x & 31;
    if (gw >= n) return;
    float* out = out_sel ? g_t2 : g_t1;
    int beg = g_roff[gw], end = g_roff[gw + 1];
    float ed = g_ed[gw];

    // phase A1: max over incoming edges (lane-parallel)
    float m = -3.4e38f;
    for (int i = beg + lane; i < end; i += 32) {
        float a = g_es[g_csr[i]] + ed;
        a = (a > 0.f) ? a : 0.2f * a;
        m = fmaxf(m, a);
    }
    #pragma unroll
    for (int o = 16; o; o >>= 1) m = fmaxf(m, __shfl_xor_sync(0xffffffffu, m, o));

    // phase A2: softmax denominator
    float ds = 0.f;
    for (int i = beg + lane; i < end; i += 32) {
        float a = g_es[g_csr[i]] + ed;
        a = (a > 0.f) ? a : 0.2f * a;
        ds += __expf(a - m);
    }
    #pragma unroll
    for (int o = 16; o; o >>= 1) ds += __shfl_xor_sync(0xffffffffu, ds, o);
    float inv = 1.0f / ds;

    // phase B: channel-parallel weighted accumulate (coalesced 128B rows)
    float acc = 0.f;
    for (int i = beg; i < end; i++) {
        int s = g_csr[i];
        float a = g_es[s] + ed;
        a = (a > 0.f) ? a : 0.2f * a;
        float w = __expf(a - m);
        acc = fmaf(w, g_lin[(size_t)s * HID + lane], acc);
    }
    acc = acc * inv + bsh[lane];
    out[(size_t)gw * HID + lane] = fmaxf(acc, 0.f);  // branch ReLU fused
}

// ---------------- linear head (optionally sigmoid) ----------------
__global__ void k_head(const float* __restrict__ lW, const float* __restrict__ lb,
                       int do_sig, float* __restrict__ out, int n) {
    __shared__ float Wsh[HID * HID];
    __shared__ float bsh[HID];
    for (int i = threadIdx.x; i < HID * HID; i += blockDim.x) Wsh[i] = lW[i];
    if (threadIdx.x < HID) bsh[threadIdx.x] = lb[threadIdx.x];
    __syncthreads();
    int gw = (blockIdx.x * blockDim.x + threadIdx.x) >> 5;
    int lane = threadIdx.x & 31;
    if (gw >= n) return;
    const float* hr = g_t2 + (size_t)gw * HID;
    float acc = bsh[lane];
    #pragma unroll
    for (int k = 0; k < HID; k++)
        acc = fmaf(hr[k], Wsh[k * HID + lane], acc);
    if (do_sig) acc = 1.0f / (1.0f + __expf(-acc));
    out[(size_t)gw * HID + lane] = acc;
}

// ---------------- launch ----------------
extern "C" void kernel_launch(void* const* d_in, const int* in_sizes, int n_in,
                              void* d_out, int out_size) {
    const float* x = (const float*)d_in[0];
    int n = in_sizes[0] / 64;

    const int T = 256;
    k_init_deg<<<(n + T - 1) / T, T>>>(n);

    // edge_index: harness supports {float32,int32,bf16}; int64 input is most
    // likely delivered as int32. Dispatch on element count to be safe:
    //   int32: in_sizes[1] == 2*E elements; int64-as-2xint32 would be 4*E.
    long long nelem = in_sizes[1];
    if (nelem == 2LL * EEMAX) {            // int32 [2, E]
        const int* ei = (const int*)d_in[1];
        int E = EEMAX;
        k_hist<int><<<(E + T - 1) / T, T>>>(ei + E, E, n);
        k_scan<<<1, 1024>>>(n);
        k_scatter<int><<<(E + n + T - 1) / T, T>>>(ei, ei + E, E, n);
    } else {                               // int64 [2, E]
        const long long* ei = (const long long*)d_in[1];
        int E = (int)(nelem / 2);
        k_hist<long long><<<(E + T - 1) / T, T>>>(ei + E, E, n);
        k_scan<<<1, 1024>>>(n);
        k_scatter<long long><<<(E + n + T - 1) / T, T>>>(ei, ei + E, E, n);
    }

    int nb = (n * 32 + T - 1) / T;  // warp per node
    for (int br = 0; br < 2; br++) {
        int o = 2 + br * 10;
        const float* W1  = (const float*)d_in[o + 0];
        const float* as1 = (const float*)d_in[o + 1];
        const float* ad1 = (const float*)d_in[o + 2];
        const float* b1  = (const float*)d_in[o + 3];
        const float* W2  = (const float*)d_in[o + 4];
        const float* as2 = (const float*)d_in[o + 5];
        const float* ad2 = (const float*)d_in[o + 6];
        const float* b2  = (const float*)d_in[o + 7];
        const float* lW  = (const float*)d_in[o + 8];
        const float* lb  = (const float*)d_in[o + 9];

        k_lin<64><<<nb, T>>>(x, 0, W1, as1, ad1, n);
        k_agg<<<nb, T>>>(b1, 0, n);
        k_lin<32><<<nb, T>>>(x, 1, W2, as2, ad2, n);
        k_agg<<<nb, T>>>(b2, 1, n);

        float* outp = (float*)d_out + (size_t)br * n * HID;
        k_head<<<nb, T>>>(lW, lb, br == 0 ? 1 : 0, outp, n);
    }
}

// round 4
// speedup vs baseline: 1.4164x; 1.4164x over previous
#include <cuda_runtime.h>

#define NN    50000
#define EEMAX 1600000
#define ETOT  (EEMAX + NN)
#define HID   32

// ---- static scratch ----
__device__ int   g_deg[NN];
__device__ int   g_roff[NN + 1];
__device__ int   g_cur[NN];
__device__ int   g_csr[ETOT];
__device__ float g_aw[ETOT];                    // per-edge score -> weight
__device__ int   g_part[64];
__device__ int   g_part2[64];
__device__ __align__(16) float g_lin[NN * HID];
__device__ float g_es[NN];
__device__ float g_ed[NN];
__device__ __align__(16) float g_t1[NN * HID];
__device__ __align__(16) float g_t2[NN * HID];

// ---------------- CSR build ----------------
__global__ void k_init_deg(int n) {
    int i = blockIdx.x * blockDim.x + threadIdx.x;
    if (i < n) g_deg[i] = 1;  // self loop pre-counted
}

// vectorized histogram: 4 edges per thread (int32 path)
__global__ void k_hist4(const int* __restrict__ dst, int E, int n) {
    int base = (blockIdx.x * blockDim.x + threadIdx.x) * 4;
    if (base + 3 < E) {
        int4 d = *(const int4*)(dst + base);
        if ((unsigned)d.x < (unsigned)n) atomicAdd(&g_deg[d.x], 1);
        if ((unsigned)d.y < (unsigned)n) atomicAdd(&g_deg[d.y], 1);
        if ((unsigned)d.z < (unsigned)n) atomicAdd(&g_deg[d.z], 1);
        if ((unsigned)d.w < (unsigned)n) atomicAdd(&g_deg[d.w], 1);
    } else {
        for (int k = base; k < E; k++) {
            int dv = dst[k];
            if ((unsigned)dv < (unsigned)n) atomicAdd(&g_deg[dv], 1);
        }
    }
}

template <typename IT>
__global__ void k_hist(const IT* __restrict__ dst, int E, int n) {
    int e = blockIdx.x * blockDim.x + threadIdx.x;
    if (e < E) {
        int d = (int)dst[e];
        if ((unsigned)d < (unsigned)n) atomicAdd(&g_deg[d], 1);
    }
}

// ---- multi-block scan: partial scans + scan of partials + fixup ----
__device__ __forceinline__ int warp_incl_scan(int x, int lane) {
    #pragma unroll
    for (int o = 1; o < 32; o <<= 1) {
        int y = __shfl_up_sync(0xffffffffu, x, o);
        if (lane >= o) x += y;
    }
    return x;
}

__global__ void kb_scan1(int n) {
    __shared__ int wsum[32];
    int tid = threadIdx.x, lane = tid & 31, wid = tid >> 5;
    int i = blockIdx.x * 1024 + tid;
    int v = (i < n) ? g_deg[i] : 0;
    int x = warp_incl_scan(v, lane);
    if (lane == 31) wsum[wid] = x;
    __syncthreads();
    if (wid == 0) wsum[lane] = warp_incl_scan(wsum[lane], lane);
    __syncthreads();
    int incl = x + (wid ? wsum[wid - 1] : 0);
    if (i < n) g_roff[i] = incl - v;           // exclusive within block
    if (tid == 1023) g_part[blockIdx.x] = incl;
}

__global__ void kb_scan2(int nb, int n) {
    __shared__ int wsum[32];
    int tid = threadIdx.x, lane = tid & 31, wid = tid >> 5;
    int v = (tid < nb) ? g_part[tid] : 0;
    int x = warp_incl_scan(v, lane);
    if (lane == 31) wsum[wid] = x;
    __syncthreads();
    if (wid == 0) wsum[lane] = warp_incl_scan(wsum[lane], lane);
    __syncthreads();
    int incl = x + (wid ? wsum[wid - 1] : 0);
    if (tid < nb) g_part2[tid] = incl - v;     // exclusive block offset
    if (tid == nb - 1) g_roff[n] = incl;       // grand total
}

__global__ void kb_scan3(int n) {
    int i = blockIdx.x * 1024 + threadIdx.x;
    if (i < n) {
        int r = g_roff[i] + g_part2[blockIdx.x];
        g_roff[i] = r;
        g_cur[i] = r;
    }
}

// vectorized scatter: 4 edges per thread (int32 path)
__global__ void k_scatter4(const int* __restrict__ src,
                           const int* __restrict__ dst, int E, int n) {
    int base = (blockIdx.x * blockDim.x + threadIdx.x) * 4;
    if (base + 3 < E) {
        int4 s4 = *(const int4*)(src + base);
        int4 d4 = *(const int4*)(dst + base);
        #pragma unroll
        for (int k = 0; k < 4; k++) {
            int s = (&s4.x)[k], d = (&d4.x)[k];
            if ((unsigned)s < (unsigned)n && (unsigned)d < (unsigned)n) {
                int pos = atomicAdd(&g_cur[d], 1);
                g_csr[pos] = s;
            }
        }
    } else {
        for (int k = base; k < E; k++) {
            int s = src[k], d = dst[k];
            if ((unsigned)s < (unsigned)n && (unsigned)d < (unsigned)n) {
                int pos = atomicAdd(&g_cur[d], 1);
                g_csr[pos] = s;
            }
        }
    }
}

template <typename IT>
__global__ void k_scatter(const IT* __restrict__ src,
                          const IT* __restrict__ dst, int E, int n) {
    int e = blockIdx.x * blockDim.x + threadIdx.x;
    if (e >= E) return;
    int s = (int)src[e], d = (int)dst[e];
    if ((unsigned)s >= (unsigned)n || (unsigned)d >= (unsigned)n) return;
    int pos = atomicAdd(&g_cur[d], 1);
    g_csr[pos] = s;
}

__global__ void k_selfloop(int n) {
    int i = blockIdx.x * blockDim.x + threadIdx.x;
    if (i < n) {
        int pos = atomicAdd(&g_cur[i], 1);
        g_csr[pos] = i;
    }
}

// ---------------- per-layer linear + attention coefficients ----------------
template <int IN_DIM>
__global__ void k_lin(const float* __restrict__ xext, int in_sel,
                      const float* __restrict__ W,
                      const float* __restrict__ a_s,
                      const float* __restrict__ a_d, int n) {
    __shared__ float Wsh[IN_DIM * HID];
    __shared__ float ash[HID], adh[HID];
    for (int i = threadIdx.x; i < IN_DIM * HID; i += blockDim.x) Wsh[i] = W[i];
    if (threadIdx.x < HID) {
        ash[threadIdx.x] = a_s[threadIdx.x];
        adh[threadIdx.x] = a_d[threadIdx.x];
    }
    __syncthreads();
    int gw = (blockIdx.x * blockDim.x + threadIdx.x) >> 5;
    int lane = threadIdx.x & 31;
    if (gw >= n) return;
    const float* X = in_sel ? g_t1 : xext;
    const float* xr = X + (size_t)gw * IN_DIM;
    float acc = 0.f;
    #pragma unroll
    for (int k = 0; k < IN_DIM; k++)
        acc = fmaf(xr[k], Wsh[k * HID + lane], acc);
    g_lin[(size_t)gw * HID + lane] = acc;
    float es = acc * ash[lane], ed = acc * adh[lane];
    #pragma unroll
    for (int o = 16; o; o >>= 1) {
        es += __shfl_xor_sync(0xffffffffu, es, o);
        ed += __shfl_xor_sync(0xffffffffu, ed, o);
    }
    if (lane == 0) { g_es[gw] = es; g_ed[gw] = ed; }
}

// ---------------- warp-per-dst softmax aggregation (ReLU + bias fused) ----
// A1: gather scores once, cache per-edge. A2: convert to exp weights in place.
// B:  4 edges x 8 channel-groups per warp, float4 row loads, no gathers/exp.
__global__ void __launch_bounds__(256) k_agg(const float* __restrict__ bias,
                                             int out_sel, int n) {
    __shared__ float bsh[HID];
    if (threadIdx.x < HID) bsh[threadIdx.x] = bias[threadIdx.x];
    __syncthreads();
    int gw = (blockIdx.x * blockDim.x + threadIdx.x) >> 5;
    int lane = threadIdx.x & 31;
    if (gw >= n) return;
    float* out = out_sel ? g_t2 : g_t1;
    int beg = g_roff[gw], end = g_roff[gw + 1];
    float ed = g_ed[gw];

    // phase A1: gather + leaky-relu, cache score, track max (lane-parallel)
    float m = -3.4e38f;
    for (int i = beg + lane; i < end; i += 32) {
        float a = g_es[g_csr[i]] + ed;
        a = (a > 0.f) ? a : 0.2f * a;
        g_aw[i] = a;
        m = fmaxf(m, a);
    }
    #pragma unroll
    for (int o = 16; o; o >>= 1) m = fmaxf(m, __shfl_xor_sync(0xffffffffu, m, o));

    // phase A2: w = exp(a - m) in place (same-lane RAW, program order), sum
    float ds = 0.f;
    for (int i = beg + lane; i < end; i += 32) {
        float w = __expf(g_aw[i] - m);
        g_aw[i] = w;
        ds += w;
    }
    #pragma unroll
    for (int o = 16; o; o >>= 1) ds += __shfl_xor_sync(0xffffffffu, ds, o);
    float inv = 1.0f / ds;

    __threadfence_block();   // cross-lane visibility of g_aw writes
    __syncwarp();

    // phase B: 4 edges x 8 channel-groups, float4 accumulate
    int eidx = lane >> 3;    // 0..3  sub-edge
    int cg   = lane & 7;     // 0..7  channel group (4 floats)
    float4 acc = make_float4(0.f, 0.f, 0.f, 0.f);
    #pragma unroll 2
    for (int i = beg; i < end; i += 4) {
        int idx = i + eidx;
        float w = 0.f;
        int s = 0;
        if (idx < end) { w = g_aw[idx]; s = g_csr[idx]; }
        const float4 r = *(const float4*)&g_lin[(size_t)s * HID + cg * 4];
        acc.x = fmaf(w, r.x, acc.x);
        acc.y = fmaf(w, r.y, acc.y);
        acc.z = fmaf(w, r.z, acc.z);
        acc.w = fmaf(w, r.w, acc.w);
    }
    // reduce across the 4 sub-edge groups (xor 8, 16)
    #pragma unroll
    for (int o = 8; o <= 16; o <<= 1) {
        acc.x += __shfl_xor_sync(0xffffffffu, acc.x, o);
        acc.y += __shfl_xor_sync(0xffffffffu, acc.y, o);
        acc.z += __shfl_xor_sync(0xffffffffu, acc.z, o);
        acc.w += __shfl_xor_sync(0xffffffffu, acc.w, o);
    }
    if (eidx == 0) {
        const float4 b4 = *(const float4*)&bsh[cg * 4];
        float4 o4;
        o4.x = fmaxf(fmaf(acc.x, inv, b4.x), 0.f);
        o4.y = fmaxf(fmaf(acc.y, inv, b4.y), 0.f);
        o4.z = fmaxf(fmaf(acc.z, inv, b4.z), 0.f);
        o4.w = fmaxf(fmaf(acc.w, inv, b4.w), 0.f);
        *(float4*)&out[(size_t)gw * HID + cg * 4] = o4;
    }
}

// ---------------- linear head (optionally sigmoid) ----------------
__global__ void k_head(const float* __restrict__ lW, const float* __restrict__ lb,
                       int do_sig, float* __restrict__ out, int n) {
    __shared__ float Wsh[HID * HID];
    __shared__ float bsh[HID];
    for (int i = threadIdx.x; i < HID * HID; i += blockDim.x) Wsh[i] = lW[i];
    if (threadIdx.x < HID) bsh[threadIdx.x] = lb[threadIdx.x];
    __syncthreads();
    int gw = (blockIdx.x * blockDim.x + threadIdx.x) >> 5;
    int lane = threadIdx.x & 31;
    if (gw >= n) return;
    const float* hr = g_t2 + (size_t)gw * HID;
    float acc = bsh[lane];
    #pragma unroll
    for (int k = 0; k < HID; k++)
        acc = fmaf(hr[k], Wsh[k * HID + lane], acc);
    if (do_sig) acc = 1.0f / (1.0f + __expf(-acc));
    out[(size_t)gw * HID + lane] = acc;
}

// ---------------- launch ----------------
extern "C" void kernel_launch(void* const* d_in, const int* in_sizes, int n_in,
                              void* d_out, int out_size) {
    const float* x = (const float*)d_in[0];
    int n = in_sizes[0] / 64;

    const int T = 256;
    k_init_deg<<<(n + T - 1) / T, T>>>(n);

    long long nelem = in_sizes[1];
    int nb_scan = (n + 1023) / 1024;
    if (nelem == 2LL * EEMAX) {            // int32 [2, E]
        const int* ei = (const int*)d_in[1];
        int E = EEMAX;
        int nt4 = (E + 3) / 4;
        k_hist4<<<(nt4 + T - 1) / T, T>>>(ei + E, E, n);
        kb_scan1<<<nb_scan, 1024>>>(n);
        kb_scan2<<<1, 1024>>>(nb_scan, n);
        kb_scan3<<<nb_scan, 1024>>>(n);
        k_scatter4<<<(nt4 + T - 1) / T, T>>>(ei, ei + E, E, n);
    } else {                               // int64 [2, E] fallback
        const long long* ei = (const long long*)d_in[1];
        int E = (int)(nelem / 2);
        k_hist<long long><<<(E + T - 1) / T, T>>>(ei + E, E, n);
        kb_scan1<<<nb_scan, 1024>>>(n);
        kb_scan2<<<1, 1024>>>(nb_scan, n);
        kb_scan3<<<nb_scan, 1024>>>(n);
        k_scatter<long long><<<(E + T - 1) / T, T>>>(ei, ei + E, E, n);
    }
    k_selfloop<<<(n + T - 1) / T, T>>>(n);

    int nb = (n * 32 + T - 1) / T;  // warp per node
    for (int br = 0; br < 2; br++) {
        int o = 2 + br * 10;
        const float* W1  = (const float*)d_in[o + 0];
        const float* as1 = (const float*)d_in[o + 1];
        const float* ad1 = (const float*)d_in[o + 2];
        const float* b1  = (const float*)d_in[o + 3];
        const float* W2  = (const float*)d_in[o + 4];
        const float* as2 = (const float*)d_in[o + 5];
        const float* ad2 = (const float*)d_in[o + 6];
        const float* b2  = (const float*)d_in[o + 7];
        const float* lW  = (const float*)d_in[o + 8];
        const float* lb  = (const float*)d_in[o + 9];

        k_lin<64><<<nb, T>>>(x, 0, W1, as1, ad1, n);
        k_agg<<<nb, T>>>(b1, 0, n);
        k_lin<32><<<nb, T>>>(x, 1, W2, as2, ad2, n);
        k_agg<<<nb, T>>>(b2, 1, n);

        float* outp = (float*)d_out + (size_t)br * n * HID;
        k_head<<<nb, T>>>(lW, lb, br == 0 ? 1 : 0, outp, n);
    }
}

// round 5
// speedup vs baseline: 1.4550x; 1.0273x over previous
#include <cuda_runtime.h>
#include <cuda_fp16.h>

#define NN    50000
#define EEMAX 1600000
#define ETOT  (EEMAX + NN)
#define HID   32

// ---- static scratch ----
__device__ int   g_deg[NN];
__device__ int   g_roff[NN + 1];
__device__ int   g_cur[NN];
__device__ int   g_csr[ETOT];
__device__ float g_aw[ETOT];                    // per-edge score -> weight
__device__ int   g_part[64];
__device__ int   g_part2[64];
__device__ __align__(16) __half g_lin[NN * HID];   // fp16 rows, 64B each
__device__ float g_es[NN];
__device__ float g_ed[NN];
__device__ __align__(16) float g_t1[NN * HID];
__device__ __align__(16) float g_t2[NN * HID];

// ---------------- CSR build ----------------
// vectorized histogram: 4 edges per thread (int32 path)
__global__ void k_hist4(const int* __restrict__ dst, int E, int n) {
    int base = (blockIdx.x * blockDim.x + threadIdx.x) * 4;
    if (base + 3 < E) {
        int4 d = *(const int4*)(dst + base);
        if ((unsigned)d.x < (unsigned)n) atomicAdd(&g_deg[d.x], 1);
        if ((unsigned)d.y < (unsigned)n) atomicAdd(&g_deg[d.y], 1);
        if ((unsigned)d.z < (unsigned)n) atomicAdd(&g_deg[d.z], 1);
        if ((unsigned)d.w < (unsigned)n) atomicAdd(&g_deg[d.w], 1);
    } else {
        for (int k = base; k < E; k++) {
            int dv = dst[k];
            if ((unsigned)dv < (unsigned)n) atomicAdd(&g_deg[dv], 1);
        }
    }
}

template <typename IT>
__global__ void k_hist(const IT* __restrict__ dst, int E, int n) {
    int e = blockIdx.x * blockDim.x + threadIdx.x;
    if (e < E) {
        int d = (int)dst[e];
        if ((unsigned)d < (unsigned)n) atomicAdd(&g_deg[d], 1);
    }
}

// ---- multi-block scan ----
__device__ __forceinline__ int warp_incl_scan(int x, int lane) {
    #pragma unroll
    for (int o = 1; o < 32; o <<= 1) {
        int y = __shfl_up_sync(0xffffffffu, x, o);
        if (lane >= o) x += y;
    }
    return x;
}

__global__ void kb_scan1(int n) {
    __shared__ int wsum[32];
    int tid = threadIdx.x, lane = tid & 31, wid = tid >> 5;
    int i = blockIdx.x * 1024 + tid;
    int v = (i < n) ? (g_deg[i] + 1) : 0;   // +1 = self loop
    int x = warp_incl_scan(v, lane);
    if (lane == 31) wsum[wid] = x;
    __syncthreads();
    if (wid == 0) wsum[lane] = warp_incl_scan(wsum[lane], lane);
    __syncthreads();
    int incl = x + (wid ? wsum[wid - 1] : 0);
    if (i < n) g_roff[i] = incl - v;           // exclusive within block
    if (tid == 1023) g_part[blockIdx.x] = incl;
}

__global__ void kb_scan2(int nb, int n) {
    __shared__ int wsum[32];
    int tid = threadIdx.x, lane = tid & 31, wid = tid >> 5;
    int v = (tid < nb) ? g_part[tid] : 0;
    int x = warp_incl_scan(v, lane);
    if (lane == 31) wsum[wid] = x;
    __syncthreads();
    if (wid == 0) wsum[lane] = warp_incl_scan(wsum[lane], lane);
    __syncthreads();
    int incl = x + (wid ? wsum[wid - 1] : 0);
    if (tid < nb) g_part2[tid] = incl - v;     // exclusive block offset
    if (tid == nb - 1) g_roff[n] = incl;       // grand total
}

// fixup + self-loop placement at row start
__global__ void kb_scan3(int n) {
    int i = blockIdx.x * 1024 + threadIdx.x;
    if (i < n) {
        int r = g_roff[i] + g_part2[blockIdx.x];
        g_roff[i] = r;
        g_csr[r]  = i;        // self loop occupies first slot
        g_cur[i]  = r + 1;
    }
}

// vectorized scatter: 4 edges per thread, atomics batched before stores
__global__ void k_scatter4(const int* __restrict__ src,
                           const int* __restrict__ dst, int E, int n) {
    int base = (blockIdx.x * blockDim.x + threadIdx.x) * 4;
    if (base + 3 < E) {
        int4 s4 = *(const int4*)(src + base);
        int4 d4 = *(const int4*)(dst + base);
        bool v0 = (unsigned)s4.x < (unsigned)n && (unsigned)d4.x < (unsigned)n;
        bool v1 = (unsigned)s4.y < (unsigned)n && (unsigned)d4.y < (unsigned)n;
        bool v2 = (unsigned)s4.z < (unsigned)n && (unsigned)d4.z < (unsigned)n;
        bool v3 = (unsigned)s4.w < (unsigned)n && (unsigned)d4.w < (unsigned)n;
        int p0 = v0 ? atomicAdd(&g_cur[d4.x], 1) : -1;
        int p1 = v1 ? atomicAdd(&g_cur[d4.y], 1) : -1;
        int p2 = v2 ? atomicAdd(&g_cur[d4.z], 1) : -1;
        int p3 = v3 ? atomicAdd(&g_cur[d4.w], 1) : -1;
        if (p0 >= 0) g_csr[p0] = s4.x;
        if (p1 >= 0) g_csr[p1] = s4.y;
        if (p2 >= 0) g_csr[p2] = s4.z;
        if (p3 >= 0) g_csr[p3] = s4.w;
    } else {
        for (int k = base; k < E; k++) {
            int s = src[k], d = dst[k];
            if ((unsigned)s < (unsigned)n && (unsigned)d < (unsigned)n) {
                int pos = atomicAdd(&g_cur[d], 1);
                g_csr[pos] = s;
            }
        }
    }
}

template <typename IT>
__global__ void k_scatter(const IT* __restrict__ src,
                          const IT* __restrict__ dst, int E, int n) {
    int e = blockIdx.x * blockDim.x + threadIdx.x;
    if (e >= E) return;
    int s = (int)src[e], d = (int)dst[e];
    if ((unsigned)s >= (unsigned)n || (unsigned)d >= (unsigned)n) return;
    int pos = atomicAdd(&g_cur[d], 1);
    g_csr[pos] = s;
}

// ---------------- per-layer linear + attention coefficients ----------------
template <int IN_DIM>
__global__ void k_lin(const float* __restrict__ xext, int in_sel,
                      const float* __restrict__ W,
                      const float* __restrict__ a_s,
                      const float* __restrict__ a_d, int n) {
    __shared__ float Wsh[IN_DIM * HID];
    __shared__ float ash[HID], adh[HID];
    for (int i = threadIdx.x; i < IN_DIM * HID; i += blockDim.x) Wsh[i] = W[i];
    if (threadIdx.x < HID) {
        ash[threadIdx.x] = a_s[threadIdx.x];
        adh[threadIdx.x] = a_d[threadIdx.x];
    }
    __syncthreads();
    int gw = (blockIdx.x * blockDim.x + threadIdx.x) >> 5;
    int lane = threadIdx.x & 31;
    if (gw >= n) return;
    const float* X = in_sel ? g_t1 : xext;
    const float* xr = X + (size_t)gw * IN_DIM;
    float acc = 0.f;
    #pragma unroll
    for (int k = 0; k < IN_DIM; k++)
        acc = fmaf(xr[k], Wsh[k * HID + lane], acc);
    g_lin[(size_t)gw * HID + lane] = __float2half_rn(acc);
    float es = acc * ash[lane], ed = acc * adh[lane];
    #pragma unroll
    for (int o = 16; o; o >>= 1) {
        es += __shfl_xor_sync(0xffffffffu, es, o);
        ed += __shfl_xor_sync(0xffffffffu, ed, o);
    }
    if (lane == 0) { g_es[gw] = es; g_ed[gw] = ed; }
}

// ---------------- warp-per-dst softmax aggregation (ReLU + bias fused) ----
// A1: gather+leaky, cache score, max. A2: w=exp(a-m) in place, sum.
// B:  8 edges x 4 channel-groups per warp; 16B fp16 row loads (8 ch/lane).
__global__ void __launch_bounds__(256) k_agg(const float* __restrict__ bias,
                                             int out_sel, int n) {
    __shared__ float bsh[HID];
    if (threadIdx.x < HID) bsh[threadIdx.x] = bias[threadIdx.x];
    __syncthreads();
    int gw = (blockIdx.x * blockDim.x + threadIdx.x) >> 5;
    int lane = threadIdx.x & 31;
    if (gw >= n) return;
    float* out = out_sel ? g_t2 : g_t1;
    int beg = g_roff[gw], end = g_roff[gw + 1];
    float ed = g_ed[gw];

    // phase A1
    float m = -3.4e38f;
    for (int i = beg + lane; i < end; i += 32) {
        float a = g_es[g_csr[i]] + ed;
        a = (a > 0.f) ? a : 0.2f * a;
        g_aw[i] = a;
        m = fmaxf(m, a);
    }
    #pragma unroll
    for (int o = 16; o; o >>= 1) m = fmaxf(m, __shfl_xor_sync(0xffffffffu, m, o));

    // phase A2
    float ds = 0.f;
    for (int i = beg + lane; i < end; i += 32) {
        float w = __expf(g_aw[i] - m);
        g_aw[i] = w;
        ds += w;
    }
    #pragma unroll
    for (int o = 16; o; o >>= 1) ds += __shfl_xor_sync(0xffffffffu, ds, o);
    float inv = 1.0f / ds;

    __threadfence_block();
    __syncwarp();

    // phase B: 8 edges x 4 channel-groups, fp16 rows
    int eidx = lane >> 2;    // 0..7  sub-edge
    int cg   = lane & 3;     // 0..3  channel group (8 halves = 16B)
    float acc[8];
    #pragma unroll
    for (int j = 0; j < 8; j++) acc[j] = 0.f;

    for (int i = beg; i < end; i += 8) {
        int idx = i + eidx;
        float w = 0.f;
        int s = 0;
        if (idx < end) { w = g_aw[idx]; s = g_csr[idx]; }
        const uint4 u = *(const uint4*)(g_lin + (size_t)s * HID + cg * 8);
        float2 f0 = __half22float2(*(const __half2*)&u.x);
        float2 f1 = __half22float2(*(const __half2*)&u.y);
        float2 f2 = __half22float2(*(const __half2*)&u.z);
        float2 f3 = __half22float2(*(const __half2*)&u.w);
        acc[0] = fmaf(w, f0.x, acc[0]);
        acc[1] = fmaf(w, f0.y, acc[1]);
        acc[2] = fmaf(w, f1.x, acc[2]);
        acc[3] = fmaf(w, f1.y, acc[3]);
        acc[4] = fmaf(w, f2.x, acc[4]);
        acc[5] = fmaf(w, f2.y, acc[5]);
        acc[6] = fmaf(w, f3.x, acc[6]);
        acc[7] = fmaf(w, f3.y, acc[7]);
    }
    // reduce across the 8 sub-edge groups (xor 4, 8, 16)
    #pragma unroll
    for (int o = 4; o <= 16; o <<= 1) {
        #pragma unroll
        for (int j = 0; j < 8; j++)
            acc[j] += __shfl_xor_sync(0xffffffffu, acc[j], o);
    }
    if (eidx == 0) {
        float4 o4a, o4b;
        o4a.x = fmaxf(fmaf(acc[0], inv, bsh[cg * 8 + 0]), 0.f);
        o4a.y = fmaxf(fmaf(acc[1], inv, bsh[cg * 8 + 1]), 0.f);
        o4a.z = fmaxf(fmaf(acc[2], inv, bsh[cg * 8 + 2]), 0.f);
        o4a.w = fmaxf(fmaf(acc[3], inv, bsh[cg * 8 + 3]), 0.f);
        o4b.x = fmaxf(fmaf(acc[4], inv, bsh[cg * 8 + 4]), 0.f);
        o4b.y = fmaxf(fmaf(acc[5], inv, bsh[cg * 8 + 5]), 0.f);
        o4b.z = fmaxf(fmaf(acc[6], inv, bsh[cg * 8 + 6]), 0.f);
        o4b.w = fmaxf(fmaf(acc[7], inv, bsh[cg * 8 + 7]), 0.f);
        *(float4*)&out[(size_t)gw * HID + cg * 8 + 0] = o4a;
        *(float4*)&out[(size_t)gw * HID + cg * 8 + 4] = o4b;
    }
}

// ---------------- linear head (optionally sigmoid) ----------------
__global__ void k_head(const float* __restrict__ lW, const float* __restrict__ lb,
                       int do_sig, float* __restrict__ out, int n) {
    __shared__ float Wsh[HID * HID];
    __shared__ float bsh[HID];
    for (int i = threadIdx.x; i < HID * HID; i += blockDim.x) Wsh[i] = lW[i];
    if (threadIdx.x < HID) bsh[threadIdx.x] = lb[threadIdx.x];
    __syncthreads();
    int gw = (blockIdx.x * blockDim.x + threadIdx.x) >> 5;
    int lane = threadIdx.x & 31;
    if (gw >= n) return;
    const float* hr = g_t2 + (size_t)gw * HID;
    float acc = bsh[lane];
    #pragma unroll
    for (int k = 0; k < HID; k++)
        acc = fmaf(hr[k], Wsh[k * HID + lane], acc);
    if (do_sig) acc = 1.0f / (1.0f + __expf(-acc));
    out[(size_t)gw * HID + lane] = acc;
}

// ---------------- launch ----------------
extern "C" void kernel_launch(void* const* d_in, const int* in_sizes, int n_in,
                              void* d_out, int out_size) {
    const float* x = (const float*)d_in[0];
    int n = in_sizes[0] / 64;

    const int T = 256;
    void* degp = nullptr;
    cudaGetSymbolAddress(&degp, g_deg);
    cudaMemsetAsync(degp, 0, n * sizeof(int));

    long long nelem = in_sizes[1];
    int nb_scan = (n + 1023) / 1024;
    if (nelem == 2LL * EEMAX) {            // int32 [2, E]
        const int* ei = (const int*)d_in[1];
        int E = EEMAX;
        int nt4 = (E + 3) / 4;
        k_hist4<<<(nt4 + T - 1) / T, T>>>(ei + E, E, n);
        kb_scan1<<<nb_scan, 1024>>>(n);
        kb_scan2<<<1, 1024>>>(nb_scan, n);
        kb_scan3<<<nb_scan, 1024>>>(n);
        k_scatter4<<<(nt4 + T - 1) / T, T>>>(ei, ei + E, E, n);
    } else {                               // int64 [2, E] fallback
        const long long* ei = (const long long*)d_in[1];
        int E = (int)(nelem / 2);
        k_hist<long long><<<(E + T - 1) / T, T>>>(ei + E, E, n);
        kb_scan1<<<nb_scan, 1024>>>(n);
        kb_scan2<<<1, 1024>>>(nb_scan, n);
        kb_scan3<<<nb_scan, 1024>>>(n);
        k_scatter<long long><<<(E + T - 1) / T, T>>>(ei, ei + E, E, n);
    }

    int nb = (n * 32 + T - 1) / T;  // warp per node
    for (int br = 0; br < 2; br++) {
        int o = 2 + br * 10;
        const float* W1  = (const float*)d_in[o + 0];
        const float* as1 = (const float*)d_in[o + 1];
        const float* ad1 = (const float*)d_in[o + 2];
        const float* b1  = (const float*)d_in[o + 3];
        const float* W2  = (const float*)d_in[o + 4];
        const float* as2 = (const float*)d_in[o + 5];
        const float* ad2 = (const float*)d_in[o + 6];
        const float* b2  = (const float*)d_in[o + 7];
        const float* lW  = (const float*)d_in[o + 8];
        const float* lb  = (const float*)d_in[o + 9];

        k_lin<64><<<nb, T>>>(x, 0, W1, as1, ad1, n);
        k_agg<<<nb, T>>>(b1, 0, n);
        k_lin<32><<<nb, T>>>(x, 1, W2, as2, ad2, n);
        k_agg<<<nb, T>>>(b2, 1, n);

        float* outp = (float*)d_out + (size_t)br * n * HID;
        k_head<<<nb, T>>>(lW, lb, br == 0 ? 1 : 0, outp, n);
    }
}

// round 7
// speedup vs baseline: 1.6555x; 1.1378x over previous
#include <cuda_runtime.h>
#include <cuda_fp16.h>

#define NN    50000
#define EEMAX 1600000
#define ETOT  (EEMAX + NN)
#define HID   32

// ---- static scratch (module zero-init; g_deg kept zero as an invariant) ----
__device__ int    g_deg[NN];
__device__ int    g_roff[NN + 1];
__device__ int    g_cur[NN];
__device__ int    g_csr[ETOT];
__device__ __align__(16) float2 g_aw[ETOT];        // per-edge weights (c,r)
__device__ int    g_part[64];
__device__ int    g_part2[64];
__device__ __align__(16) __half2 g_lin[NN * HID];  // per channel: (c,r)
__device__ __align__(8)  float2 g_es[NN];          // (es_c, es_r)
__device__ __align__(8)  float2 g_ed[NN];          // (ed_c, ed_r)
__device__ __align__(16) float g_t1c[NN * HID];
__device__ __align__(16) float g_t1r[NN * HID];
__device__ __align__(16) float g_t2c[NN * HID];
__device__ __align__(16) float g_t2r[NN * HID];

// ---------------- CSR build ----------------
__global__ void k_hist8(const int* __restrict__ dst, int E, int n) {
    int base = (blockIdx.x * blockDim.x + threadIdx.x) * 8;
    if (base + 7 < E) {
        int4 a = *(const int4*)(dst + base);
        int4 b = *(const int4*)(dst + base + 4);
        #pragma unroll
        for (int k = 0; k < 4; k++) {
            int d0 = (&a.x)[k], d1 = (&b.x)[k];
            if ((unsigned)d0 < (unsigned)n) atomicAdd(&g_deg[d0], 1);
            if ((unsigned)d1 < (unsigned)n) atomicAdd(&g_deg[d1], 1);
        }
    } else {
        for (int k = base; k < E; k++) {
            int dv = dst[k];
            if ((unsigned)dv < (unsigned)n) atomicAdd(&g_deg[dv], 1);
        }
    }
}

__global__ void k_hist64(const long long* __restrict__ dst, int E, int n) {
    int e = blockIdx.x * blockDim.x + threadIdx.x;
    if (e < E) {
        int d = (int)dst[e];
        if ((unsigned)d < (unsigned)n) atomicAdd(&g_deg[d], 1);
    }
}

__device__ __forceinline__ int warp_incl_scan(int x, int lane) {
    #pragma unroll
    for (int o = 1; o < 32; o <<= 1) {
        int y = __shfl_up_sync(0xffffffffu, x, o);
        if (lane >= o) x += y;
    }
    return x;
}

// scan pass 1: also re-zeroes g_deg (restores invariant; no memset launch)
__global__ void kb_scan1(int n) {
    __shared__ int wsum[32];
    int tid = threadIdx.x, lane = tid & 31, wid = tid >> 5;
    int i = blockIdx.x * 1024 + tid;
    int v = 0;
    if (i < n) { v = g_deg[i] + 1; g_deg[i] = 0; }   // +1 = self loop
    int x = warp_incl_scan(v, lane);
    if (lane == 31) wsum[wid] = x;
    __syncthreads();
    if (wid == 0) wsum[lane] = warp_incl_scan(wsum[lane], lane);
    __syncthreads();
    int incl = x + (wid ? wsum[wid - 1] : 0);
    if (i < n) g_roff[i] = incl - v;
    if (tid == 1023) g_part[blockIdx.x] = incl;
}

__global__ void kb_scan2(int nb, int n) {
    __shared__ int wsum[32];
    int tid = threadIdx.x, lane = tid & 31, wid = tid >> 5;
    int v = (tid < nb) ? g_part[tid] : 0;
    int x = warp_incl_scan(v, lane);
    if (lane == 31) wsum[wid] = x;
    __syncthreads();
    if (wid == 0) wsum[lane] = warp_incl_scan(wsum[lane], lane);
    __syncthreads();
    int incl = x + (wid ? wsum[wid - 1] : 0);
    if (tid < nb) g_part2[tid] = incl - v;
    if (tid == nb - 1) g_roff[n] = incl;
}

__global__ void kb_scan3(int n) {
    int i = blockIdx.x * 1024 + threadIdx.x;
    if (i < n) {
        int r = g_roff[i] + g_part2[blockIdx.x];
        g_roff[i] = r;
        g_csr[r]  = i;        // self loop in first slot
        g_cur[i]  = r + 1;
    }
}

__global__ void k_scatter8(const int* __restrict__ src,
                           const int* __restrict__ dst, int E, int n) {
    int base = (blockIdx.x * blockDim.x + threadIdx.x) * 8;
    if (base + 7 < E) {
        int4 sa = *(const int4*)(src + base);
        int4 sb = *(const int4*)(src + base + 4);
        int4 da = *(const int4*)(dst + base);
        int4 db = *(const int4*)(dst + base + 4);
        int s[8] = {sa.x, sa.y, sa.z, sa.w, sb.x, sb.y, sb.z, sb.w};
        int d[8] = {da.x, da.y, da.z, da.w, db.x, db.y, db.z, db.w};
        int p[8];
        #pragma unroll
        for (int k = 0; k < 8; k++) {
            bool ok = (unsigned)s[k] < (unsigned)n && (unsigned)d[k] < (unsigned)n;
            p[k] = ok ? atomicAdd(&g_cur[d[k]], 1) : -1;
        }
        #pragma unroll
        for (int k = 0; k < 8; k++)
            if (p[k] >= 0) g_csr[p[k]] = s[k];
    } else {
        for (int k = base; k < E; k++) {
            int s = src[k], d = dst[k];
            if ((unsigned)s < (unsigned)n && (unsigned)d < (unsigned)n) {
                int pos = atomicAdd(&g_cur[d], 1);
                g_csr[pos] = s;
            }
        }
    }
}

__global__ void k_scatter64(const long long* __restrict__ src,
                            const long long* __restrict__ dst, int E, int n) {
    int e = blockIdx.x * blockDim.x + threadIdx.x;
    if (e >= E) return;
    int s = (int)src[e], d = (int)dst[e];
    if ((unsigned)s >= (unsigned)n || (unsigned)d >= (unsigned)n) return;
    int pos = atomicAdd(&g_cur[d], 1);
    g_csr[pos] = s;
}

// ------------- fused two-branch linear + attention coefficients -------------
__global__ void __launch_bounds__(256) k_lin1(
    const float* __restrict__ x,
    const float* __restrict__ Wc, const float* __restrict__ asc_, const float* __restrict__ adc,
    const float* __restrict__ Wr, const float* __restrict__ asr_, const float* __restrict__ adr,
    int n) {
    __shared__ float Wsc[64 * HID], Wsr[64 * HID];
    __shared__ float av[4 * HID];
    for (int i = threadIdx.x; i < 64 * HID; i += blockDim.x) {
        Wsc[i] = Wc[i]; Wsr[i] = Wr[i];
    }
    if (threadIdx.x < HID) {
        av[threadIdx.x]           = asc_[threadIdx.x];
        av[HID + threadIdx.x]     = adc[threadIdx.x];
        av[2 * HID + threadIdx.x] = asr_[threadIdx.x];
        av[3 * HID + threadIdx.x] = adr[threadIdx.x];
    }
    __syncthreads();
    int gw = (blockIdx.x * blockDim.x + threadIdx.x) >> 5;
    int lane = threadIdx.x & 31;
    if (gw >= n) return;
    const float* xr = x + (size_t)gw * 64;
    float ac = 0.f, ar = 0.f;
    #pragma unroll
    for (int k = 0; k < 64; k++) {
        float xv = xr[k];
        ac = fmaf(xv, Wsc[k * HID + lane], ac);
        ar = fmaf(xv, Wsr[k * HID + lane], ar);
    }
    g_lin[(size_t)gw * HID + lane] = __floats2half2_rn(ac, ar);
    float e0 = ac * av[lane], e1 = ac * av[HID + lane];
    float e2 = ar * av[2 * HID + lane], e3 = ar * av[3 * HID + lane];
    #pragma unroll
    for (int o = 16; o; o >>= 1) {
        e0 += __shfl_xor_sync(0xffffffffu, e0, o);
        e1 += __shfl_xor_sync(0xffffffffu, e1, o);
        e2 += __shfl_xor_sync(0xffffffffu, e2, o);
        e3 += __shfl_xor_sync(0xffffffffu, e3, o);
    }
    if (lane == 0) {
        g_es[gw] = make_float2(e0, e2);
        g_ed[gw] = make_float2(e1, e3);
    }
}

__global__ void __launch_bounds__(256) k_lin2(
    const float* __restrict__ Wc, const float* __restrict__ asc_, const float* __restrict__ adc,
    const float* __restrict__ Wr, const float* __restrict__ asr_, const float* __restrict__ adr,
    int n) {
    __shared__ float Wsc[HID * HID], Wsr[HID * HID];
    __shared__ float av[4 * HID];
    for (int i = threadIdx.x; i < HID * HID; i += blockDim.x) {
        Wsc[i] = Wc[i]; Wsr[i] = Wr[i];
    }
    if (threadIdx.x < HID) {
        av[threadIdx.x]           = asc_[threadIdx.x];
        av[HID + threadIdx.x]     = adc[threadIdx.x];
        av[2 * HID + threadIdx.x] = asr_[threadIdx.x];
        av[3 * HID + threadIdx.x] = adr[threadIdx.x];
    }
    __syncthreads();
    int gw = (blockIdx.x * blockDim.x + threadIdx.x) >> 5;
    int lane = threadIdx.x & 31;
    if (gw >= n) return;
    const float* hc = g_t1c + (size_t)gw * HID;
    const float* hr = g_t1r + (size_t)gw * HID;
    float ac = 0.f, ar = 0.f;
    #pragma unroll
    for (int k = 0; k < HID; k++) {
        ac = fmaf(hc[k], Wsc[k * HID + lane], ac);
        ar = fmaf(hr[k], Wsr[k * HID + lane], ar);
    }
    g_lin[(size_t)gw * HID + lane] = __floats2half2_rn(ac, ar);
    float e0 = ac * av[lane], e1 = ac * av[HID + lane];
    float e2 = ar * av[2 * HID + lane], e3 = ar * av[3 * HID + lane];
    #pragma unroll
    for (int o = 16; o; o >>= 1) {
        e0 += __shfl_xor_sync(0xffffffffu, e0, o);
        e1 += __shfl_xor_sync(0xffffffffu, e1, o);
        e2 += __shfl_xor_sync(0xffffffffu, e2, o);
        e3 += __shfl_xor_sync(0xffffffffu, e3, o);
    }
    if (lane == 0) {
        g_es[gw] = make_float2(e0, e2);
        g_ed[gw] = make_float2(e1, e3);
    }
}

// ---------- fused two-branch warp-per-dst softmax aggregation ----------
// No max-pass: coef = exp(a)/sum(exp(a)) (scores bounded; fp32-safe).
__global__ void __launch_bounds__(256) k_agg(const float* __restrict__ bc,
                                             const float* __restrict__ br,
                                             int out_sel, int n) {
    __shared__ float bsh[2 * HID];
    if (threadIdx.x < HID) {
        bsh[threadIdx.x]       = bc[threadIdx.x];
        bsh[HID + threadIdx.x] = br[threadIdx.x];
    }
    __syncthreads();
    int gw = (blockIdx.x * blockDim.x + threadIdx.x) >> 5;
    int lane = threadIdx.x & 31;
    if (gw >= n) return;
    float* outc = out_sel ? g_t2c : g_t1c;
    float* outr = out_sel ? g_t2r : g_t1r;
    int beg = g_roff[gw], end = g_roff[gw + 1];
    float2 ed = g_ed[gw];

    // phase A: gather es, leaky, exp, cache weight, sum (both branches)
    float sc = 0.f, sr = 0.f;
    for (int i = beg + lane; i < end; i += 32) {
        float2 e = g_es[g_csr[i]];
        float ac_ = e.x + ed.x; ac_ = (ac_ > 0.f) ? ac_ : 0.2f * ac_;
        float ar_ = e.y + ed.y; ar_ = (ar_ > 0.f) ? ar_ : 0.2f * ar_;
        float wc = __expf(ac_), wr = __expf(ar_);
        g_aw[i] = make_float2(wc, wr);
        sc += wc; sr += wr;
    }
    #pragma unroll
    for (int o = 16; o; o >>= 1) {
        sc += __shfl_xor_sync(0xffffffffu, sc, o);
        sr += __shfl_xor_sync(0xffffffffu, sr, o);
    }
    float invc = 1.0f / sc, invr = 1.0f / sr;

    __threadfence_block();
    __syncwarp();

    // phase B: 8 edges x 4 channel-groups; each lane loads 32B = 8 channels
    // of the (c,r)-packed row -> full 128B row covered by 4 lanes.
    int eidx = lane >> 2;    // 0..7 sub-edge
    int cg   = lane & 3;     // 0..3 channel group (8 channels)
    float accc[8], accr[8];
    #pragma unroll
    for (int j = 0; j < 8; j++) { accc[j] = 0.f; accr[j] = 0.f; }
    for (int i = beg; i < end; i += 8) {
        int idx = i + eidx;
        float2 w = make_float2(0.f, 0.f);
        int s = 0;
        if (idx < end) { w = g_aw[idx]; s = g_csr[idx]; }
        const __half2* row = g_lin + (size_t)s * HID + cg * 8;
        const uint4 u0 = *(const uint4*)(row);
        const uint4 u1 = *(const uint4*)(row + 4);
        float2 f0 = __half22float2(*(const __half2*)&u0.x);
        float2 f1 = __half22float2(*(const __half2*)&u0.y);
        float2 f2 = __half22float2(*(const __half2*)&u0.z);
        float2 f3 = __half22float2(*(const __half2*)&u0.w);
        float2 f4 = __half22float2(*(const __half2*)&u1.x);
        float2 f5 = __half22float2(*(const __half2*)&u1.y);
        float2 f6 = __half22float2(*(const __half2*)&u1.z);
        float2 f7 = __half22float2(*(const __half2*)&u1.w);
        accc[0] = fmaf(w.x, f0.x, accc[0]); accr[0] = fmaf(w.y, f0.y, accr[0]);
        accc[1] = fmaf(w.x, f1.x, accc[1]); accr[1] = fmaf(w.y, f1.y, accr[1]);
        accc[2] = fmaf(w.x, f2.x, accc[2]); accr[2] = fmaf(w.y, f2.y, accr[2]);
        accc[3] = fmaf(w.x, f3.x, accc[3]); accr[3] = fmaf(w.y, f3.y, accr[3]);
        accc[4] = fmaf(w.x, f4.x, accc[4]); accr[4] = fmaf(w.y, f4.y, accr[4]);
        accc[5] = fmaf(w.x, f5.x, accc[5]); accr[5] = fmaf(w.y, f5.y, accr[5]);
        accc[6] = fmaf(w.x, f6.x, accc[6]); accr[6] = fmaf(w.y, f6.y, accr[6]);
        accc[7] = fmaf(w.x, f7.x, accc[7]); accr[7] = fmaf(w.y, f7.y, accr[7]);
    }
    #pragma unroll
    for (int o = 4; o <= 16; o <<= 1) {
        #pragma unroll
        for (int j = 0; j < 8; j++) {
            accc[j] += __shfl_xor_sync(0xffffffffu, accc[j], o);
            accr[j] += __shfl_xor_sync(0xffffffffu, accr[j], o);
        }
    }
    if (eidx == 0) {   // lanes 0..3 write channels cg*8 .. cg*8+7
        float4 oc0, oc1, or0, or1;
        oc0.x = fmaxf(fmaf(accc[0], invc, bsh[cg * 8 + 0]), 0.f);
        oc0.y = fmaxf(fmaf(accc[1], invc, bsh[cg * 8 + 1]), 0.f);
        oc0.z = fmaxf(fmaf(accc[2], invc, bsh[cg * 8 + 2]), 0.f);
        oc0.w = fmaxf(fmaf(accc[3], invc, bsh[cg * 8 + 3]), 0.f);
        oc1.x = fmaxf(fmaf(accc[4], invc, bsh[cg * 8 + 4]), 0.f);
        oc1.y = fmaxf(fmaf(accc[5], invc, bsh[cg * 8 + 5]), 0.f);
        oc1.z = fmaxf(fmaf(accc[6], invc, bsh[cg * 8 + 6]), 0.f);
        oc1.w = fmaxf(fmaf(accc[7], invc, bsh[cg * 8 + 7]), 0.f);
        or0.x = fmaxf(fmaf(accr[0], invr, bsh[HID + cg * 8 + 0]), 0.f);
        or0.y = fmaxf(fmaf(accr[1], invr, bsh[HID + cg * 8 + 1]), 0.f);
        or0.z = fmaxf(fmaf(accr[2], invr, bsh[HID + cg * 8 + 2]), 0.f);
        or0.w = fmaxf(fmaf(accr[3], invr, bsh[HID + cg * 8 + 3]), 0.f);
        or1.x = fmaxf(fmaf(accr[4], invr, bsh[HID + cg * 8 + 4]), 0.f);
        or1.y = fmaxf(fmaf(accr[5], invr, bsh[HID + cg * 8 + 5]), 0.f);
        or1.z = fmaxf(fmaf(accr[6], invr, bsh[HID + cg * 8 + 6]), 0.f);
        or1.w = fmaxf(fmaf(accr[7], invr, bsh[HID + cg * 8 + 7]), 0.f);
        *(float4*)&outc[(size_t)gw * HID + cg * 8 + 0] = oc0;
        *(float4*)&outc[(size_t)gw * HID + cg * 8 + 4] = oc1;
        *(float4*)&outr[(size_t)gw * HID + cg * 8 + 0] = or0;
        *(float4*)&outr[(size_t)gw * HID + cg * 8 + 4] = or1;
    }
}

// ---------------- fused heads: sigmoid(c) and linear(r) ----------------
__global__ void __launch_bounds__(256) k_head(
    const float* __restrict__ lWc, const float* __restrict__ lbc,
    const float* __restrict__ lWr, const float* __restrict__ lbr,
    float* __restrict__ out, int n) {
    __shared__ float Wsc[HID * HID], Wsr[HID * HID];
    __shared__ float bsh[2 * HID];
    for (int i = threadIdx.x; i < HID * HID; i += blockDim.x) {
        Wsc[i] = lWc[i]; Wsr[i] = lWr[i];
    }
    if (threadIdx.x < HID) {
        bsh[threadIdx.x]       = lbc[threadIdx.x];
        bsh[HID + threadIdx.x] = lbr[threadIdx.x];
    }
    __syncthreads();
    int gw = (blockIdx.x * blockDim.x + threadIdx.x) >> 5;
    int lane = threadIdx.x & 31;
    if (gw >= n) return;
    const float* hc = g_t2c + (size_t)gw * HID;
    const float* hr = g_t2r + (size_t)gw * HID;
    float ac = bsh[lane], ar = bsh[HID + lane];
    #pragma unroll
    for (int k = 0; k < HID; k++) {
        ac = fmaf(hc[k], Wsc[k * HID + lane], ac);
        ar = fmaf(hr[k], Wsr[k * HID + lane], ar);
    }
    out[(size_t)gw * HID + lane] = 1.0f / (1.0f + __expf(-ac));
    out[(size_t)n * HID + (size_t)gw * HID + lane] = ar;
}

// ---------------- launch ----------------
extern "C" void kernel_launch(void* const* d_in, const int* in_sizes, int n_in,
                              void* d_out, int out_size) {
    const float* x = (const float*)d_in[0];
    int n = in_sizes[0] / 64;

    const int T = 256;
    long long nelem = in_sizes[1];
    int nb_scan = (n + 1023) / 1024;
    if (nelem == 2LL * EEMAX) {            // int32 [2, E]
        const int* ei = (const int*)d_in[1];
        int E = EEMAX;
        int nt8 = (E + 7) / 8;
        k_hist8<<<(nt8 + T - 1) / T, T>>>(ei + E, E, n);
        kb_scan1<<<nb_scan, 1024>>>(n);
        kb_scan2<<<1, 1024>>>(nb_scan, n);
        kb_scan3<<<nb_scan, 1024>>>(n);
        k_scatter8<<<(nt8 + T - 1) / T, T>>>(ei, ei + E, E, n);
    } else {                               // int64 [2, E] fallback
        const long long* ei = (const long long*)d_in[1];
        int E = (int)(nelem / 2);
        k_hist64<<<(E + T - 1) / T, T>>>(ei + E, E, n);
        kb_scan1<<<nb_scan, 1024>>>(n);
        kb_scan2<<<1, 1024>>>(nb_scan, n);
        kb_scan3<<<nb_scan, 1024>>>(n);
        k_scatter64<<<(E + T - 1) / T, T>>>(ei, ei + E, E, n);
    }

    // params: c at d_in[2..11], r at d_in[12..21]
    const float** c = (const float**)(d_in + 2);
    const float** r = (const float**)(d_in + 12);

    int nb = (n * 32 + T - 1) / T;  // warp per node
    k_lin1<<<nb, T>>>(x, c[0], c[1], c[2], r[0], r[1], r[2], n);
    k_agg<<<nb, T>>>(c[3], r[3], 0, n);
    k_lin2<<<nb, T>>>(c[4], c[5], c[6], r[4], r[5], r[6], n);
    k_agg<<<nb, T>>>(c[7], r[7], 1, n);
    k_head<<<nb, T>>>(c[8], c[9], r[8], r[9], (float*)d_out, n);
}

// round 8
// speedup vs baseline: 1.7130x; 1.0348x over previous
#include <cuda_runtime.h>
#include <cuda_fp16.h>

#define NN    50000
#define EEMAX 1600000
#define ETOT  (EEMAX + NN)
#define HID   32

// ---- static scratch (module zero-init; g_deg kept zero as an invariant) ----
__device__ int    g_deg[NN];
__device__ int    g_roff[NN + 1];
__device__ int    g_cur[NN];
__device__ int    g_csr[ETOT];
__device__ int    g_part[64];
__device__ int    g_part2[64];
__device__ __align__(16) __half2 g_lin[NN * HID];  // per channel: (c,r)
__device__ __align__(8)  float2 g_es[NN];          // (es_c, es_r)
__device__ __align__(8)  float2 g_ed[NN];          // (ed_c, ed_r)
__device__ __align__(16) float g_t1c[NN * HID];
__device__ __align__(16) float g_t1r[NN * HID];
__device__ __align__(16) float g_t2c[NN * HID];
__device__ __align__(16) float g_t2r[NN * HID];

// ---------------- CSR build ----------------
__global__ void k_hist8(const int* __restrict__ dst, int E, int n) {
    int base = (blockIdx.x * blockDim.x + threadIdx.x) * 8;
    if (base + 7 < E) {
        int4 a = *(const int4*)(dst + base);
        int4 b = *(const int4*)(dst + base + 4);
        #pragma unroll
        for (int k = 0; k < 4; k++) {
            int d0 = (&a.x)[k], d1 = (&b.x)[k];
            if ((unsigned)d0 < (unsigned)n) atomicAdd(&g_deg[d0], 1);
            if ((unsigned)d1 < (unsigned)n) atomicAdd(&g_deg[d1], 1);
        }
    } else {
        for (int k = base; k < E; k++) {
            int dv = dst[k];
            if ((unsigned)dv < (unsigned)n) atomicAdd(&g_deg[dv], 1);
        }
    }
}

__global__ void k_hist64(const long long* __restrict__ dst, int E, int n) {
    int e = blockIdx.x * blockDim.x + threadIdx.x;
    if (e < E) {
        int d = (int)dst[e];
        if ((unsigned)d < (unsigned)n) atomicAdd(&g_deg[d], 1);
    }
}

__device__ __forceinline__ int warp_incl_scan(int x, int lane) {
    #pragma unroll
    for (int o = 1; o < 32; o <<= 1) {
        int y = __shfl_up_sync(0xffffffffu, x, o);
        if (lane >= o) x += y;
    }
    return x;
}

// scan pass 1: also re-zeroes g_deg (restores invariant; no memset launch)
__global__ void kb_scan1(int n) {
    __shared__ int wsum[32];
    int tid = threadIdx.x, lane = tid & 31, wid = tid >> 5;
    int i = blockIdx.x * 1024 + tid;
    int v = 0;
    if (i < n) { v = g_deg[i] + 1; g_deg[i] = 0; }   // +1 = self loop
    int x = warp_incl_scan(v, lane);
    if (lane == 31) wsum[wid] = x;
    __syncthreads();
    if (wid == 0) wsum[lane] = warp_incl_scan(wsum[lane], lane);
    __syncthreads();
    int incl = x + (wid ? wsum[wid - 1] : 0);
    if (i < n) g_roff[i] = incl - v;
    if (tid == 1023) g_part[blockIdx.x] = incl;
}

__global__ void kb_scan2(int nb, int n) {
    __shared__ int wsum[32];
    int tid = threadIdx.x, lane = tid & 31, wid = tid >> 5;
    int v = (tid < nb) ? g_part[tid] : 0;
    int x = warp_incl_scan(v, lane);
    if (lane == 31) wsum[wid] = x;
    __syncthreads();
    if (wid == 0) wsum[lane] = warp_incl_scan(wsum[lane], lane);
    __syncthreads();
    int incl = x + (wid ? wsum[wid - 1] : 0);
    if (tid < nb) g_part2[tid] = incl - v;
    if (tid == nb - 1) g_roff[n] = incl;
}

__global__ void kb_scan3(int n) {
    int i = blockIdx.x * 1024 + threadIdx.x;
    if (i < n) {
        int r = g_roff[i] + g_part2[blockIdx.x];
        g_roff[i] = r;
        g_csr[r]  = i;        // self loop in first slot
        g_cur[i]  = r + 1;
    }
}

__global__ void k_scatter8(const int* __restrict__ src,
                           const int* __restrict__ dst, int E, int n) {
    int base = (blockIdx.x * blockDim.x + threadIdx.x) * 8;
    if (base + 7 < E) {
        int4 sa = *(const int4*)(src + base);
        int4 sb = *(const int4*)(src + base + 4);
        int4 da = *(const int4*)(dst + base);
        int4 db = *(const int4*)(dst + base + 4);
        int s[8] = {sa.x, sa.y, sa.z, sa.w, sb.x, sb.y, sb.z, sb.w};
        int d[8] = {da.x, da.y, da.z, da.w, db.x, db.y, db.z, db.w};
        int p[8];
        #pragma unroll
        for (int k = 0; k < 8; k++) {
            bool ok = (unsigned)s[k] < (unsigned)n && (unsigned)d[k] < (unsigned)n;
            p[k] = ok ? atomicAdd(&g_cur[d[k]], 1) : -1;
        }
        #pragma unroll
        for (int k = 0; k < 8; k++)
            if (p[k] >= 0) g_csr[p[k]] = s[k];
    } else {
        for (int k = base; k < E; k++) {
            int s = src[k], d = dst[k];
            if ((unsigned)s < (unsigned)n && (unsigned)d < (unsigned)n) {
                int pos = atomicAdd(&g_cur[d], 1);
                g_csr[pos] = s;
            }
        }
    }
}

__global__ void k_scatter64(const long long* __restrict__ src,
                            const long long* __restrict__ dst, int E, int n) {
    int e = blockIdx.x * blockDim.x + threadIdx.x;
    if (e >= E) return;
    int s = (int)src[e], d = (int)dst[e];
    if ((unsigned)s >= (unsigned)n || (unsigned)d >= (unsigned)n) return;
    int pos = atomicAdd(&g_cur[d], 1);
    g_csr[pos] = s;
}

// ------------- fused two-branch linear + attention coefficients -------------
__global__ void __launch_bounds__(256) k_lin1(
    const float* __restrict__ x,
    const float* __restrict__ Wc, const float* __restrict__ asc_, const float* __restrict__ adc,
    const float* __restrict__ Wr, const float* __restrict__ asr_, const float* __restrict__ adr,
    int n) {
    __shared__ float Wsc[64 * HID], Wsr[64 * HID];
    __shared__ float av[4 * HID];
    for (int i = threadIdx.x; i < 64 * HID; i += blockDim.x) {
        Wsc[i] = Wc[i]; Wsr[i] = Wr[i];
    }
    if (threadIdx.x < HID) {
        av[threadIdx.x]           = asc_[threadIdx.x];
        av[HID + threadIdx.x]     = adc[threadIdx.x];
        av[2 * HID + threadIdx.x] = asr_[threadIdx.x];
        av[3 * HID + threadIdx.x] = adr[threadIdx.x];
    }
    __syncthreads();
    int gw = (blockIdx.x * blockDim.x + threadIdx.x) >> 5;
    int lane = threadIdx.x & 31;
    if (gw >= n) return;
    const float* xr = x + (size_t)gw * 64;
    float ac = 0.f, ar = 0.f;
    #pragma unroll
    for (int k = 0; k < 64; k++) {
        float xv = xr[k];
        ac = fmaf(xv, Wsc[k * HID + lane], ac);
        ar = fmaf(xv, Wsr[k * HID + lane], ar);
    }
    g_lin[(size_t)gw * HID + lane] = __floats2half2_rn(ac, ar);
    float e0 = ac * av[lane], e1 = ac * av[HID + lane];
    float e2 = ar * av[2 * HID + lane], e3 = ar * av[3 * HID + lane];
    #pragma unroll
    for (int o = 16; o; o >>= 1) {
        e0 += __shfl_xor_sync(0xffffffffu, e0, o);
        e1 += __shfl_xor_sync(0xffffffffu, e1, o);
        e2 += __shfl_xor_sync(0xffffffffu, e2, o);
        e3 += __shfl_xor_sync(0xffffffffu, e3, o);
    }
    if (lane == 0) {
        g_es[gw] = make_float2(e0, e2);
        g_ed[gw] = make_float2(e1, e3);
    }
}

__global__ void __launch_bounds__(256) k_lin2(
    const float* __restrict__ Wc, const float* __restrict__ asc_, const float* __restrict__ adc,
    const float* __restrict__ Wr, const float* __restrict__ asr_, const float* __restrict__ adr,
    int n) {
    __shared__ float Wsc[HID * HID], Wsr[HID * HID];
    __shared__ float av[4 * HID];
    for (int i = threadIdx.x; i < HID * HID; i += blockDim.x) {
        Wsc[i] = Wc[i]; Wsr[i] = Wr[i];
    }
    if (threadIdx.x < HID) {
        av[threadIdx.x]           = asc_[threadIdx.x];
        av[HID + threadIdx.x]     = adc[threadIdx.x];
        av[2 * HID + threadIdx.x] = asr_[threadIdx.x];
        av[3 * HID + threadIdx.x] = adr[threadIdx.x];
    }
    __syncthreads();
    int gw = (blockIdx.x * blockDim.x + threadIdx.x) >> 5;
    int lane = threadIdx.x & 31;
    if (gw >= n) return;
    const float* hc = g_t1c + (size_t)gw * HID;
    const float* hr = g_t1r + (size_t)gw * HID;
    float ac = 0.f, ar = 0.f;
    #pragma unroll
    for (int k = 0; k < HID; k++) {
        ac = fmaf(hc[k], Wsc[k * HID + lane], ac);
        ar = fmaf(hr[k], Wsr[k * HID + lane], ar);
    }
    g_lin[(size_t)gw * HID + lane] = __floats2half2_rn(ac, ar);
    float e0 = ac * av[lane], e1 = ac * av[HID + lane];
    float e2 = ar * av[2 * HID + lane], e3 = ar * av[3 * HID + lane];
    #pragma unroll
    for (int o = 16; o; o >>= 1) {
        e0 += __shfl_xor_sync(0xffffffffu, e0, o);
        e1 += __shfl_xor_sync(0xffffffffu, e1, o);
        e2 += __shfl_xor_sync(0xffffffffu, e2, o);
        e3 += __shfl_xor_sync(0xffffffffu, e3, o);
    }
    if (lane == 0) {
        g_es[gw] = make_float2(e0, e2);
        g_ed[gw] = make_float2(e2 == e2 ? e1 : e1, e3);  // (e1, e3)
    }
}

// ---------- fused two-branch SINGLE-PASS softmax aggregation ----------
// out = sum(w_i * h_i) / sum(w_i); w = exp(leaky(es[src]+ed)).
// Per 32-edge chunk: lanes compute w lane-parallel (1 exp/edge/branch),
// then 4 shfl-redistributed sub-iterations accumulate 8 edges x 4 cgroups.
__global__ void __launch_bounds__(256) k_agg(const float* __restrict__ bc,
                                             const float* __restrict__ br,
                                             int out_sel, int n) {
    __shared__ float bsh[2 * HID];
    if (threadIdx.x < HID) {
        bsh[threadIdx.x]       = bc[threadIdx.x];
        bsh[HID + threadIdx.x] = br[threadIdx.x];
    }
    __syncthreads();
    int gw = (blockIdx.x * blockDim.x + threadIdx.x) >> 5;
    int lane = threadIdx.x & 31;
    if (gw >= n) return;
    float* outc = out_sel ? g_t2c : g_t1c;
    float* outr = out_sel ? g_t2r : g_t1r;
    int beg = g_roff[gw], end = g_roff[gw + 1];
    float2 ed = g_ed[gw];

    int eidx = lane >> 2;    // 0..7 sub-edge within group of 8
    int cg   = lane & 3;     // 0..3 channel group (8 channels, 32B)
    float sc = 0.f, sr = 0.f;
    float accc[8], accr[8];
    #pragma unroll
    for (int j = 0; j < 8; j++) { accc[j] = 0.f; accr[j] = 0.f; }

    for (int base = beg; base < end; base += 32) {
        // lane-parallel weight computation for up to 32 edges
        int i = base + lane;
        int s_l = 0;
        float wc = 0.f, wr = 0.f;
        if (i < end) {
            s_l = g_csr[i];
            float2 e = g_es[s_l];
            float ac_ = e.x + ed.x; ac_ = (ac_ > 0.f) ? ac_ : 0.2f * ac_;
            float ar_ = e.y + ed.y; ar_ = (ar_ > 0.f) ? ar_ : 0.2f * ar_;
            wc = __expf(ac_); wr = __expf(ar_);
        }
        sc += wc; sr += wr;

        // redistribute + accumulate: 4 sub-iterations of 8 edges
        #pragma unroll
        for (int j = 0; j < 4; j++) {
            if (base + j * 8 >= end) break;             // warp-uniform
            int lsrc = j * 8 + eidx;
            float wcx = __shfl_sync(0xffffffffu, wc, lsrc);   // 0 if invalid
            float wrx = __shfl_sync(0xffffffffu, wr, lsrc);
            int   s   = __shfl_sync(0xffffffffu, s_l, lsrc);  // 0 if invalid
            const __half2* row = g_lin + (size_t)s * HID + cg * 8;
            const uint4 u0 = *(const uint4*)(row);
            const uint4 u1 = *(const uint4*)(row + 4);
            float2 f0 = __half22float2(*(const __half2*)&u0.x);
            float2 f1 = __half22float2(*(const __half2*)&u0.y);
            float2 f2 = __half22float2(*(const __half2*)&u0.z);
            float2 f3 = __half22float2(*(const __half2*)&u0.w);
            float2 f4 = __half22float2(*(const __half2*)&u1.x);
            float2 f5 = __half22float2(*(const __half2*)&u1.y);
            float2 f6 = __half22float2(*(const __half2*)&u1.z);
            float2 f7 = __half22float2(*(const __half2*)&u1.w);
            accc[0] = fmaf(wcx, f0.x, accc[0]); accr[0] = fmaf(wrx, f0.y, accr[0]);
            accc[1] = fmaf(wcx, f1.x, accc[1]); accr[1] = fmaf(wrx, f1.y, accr[1]);
            accc[2] = fmaf(wcx, f2.x, accc[2]); accr[2] = fmaf(wrx, f2.y, accr[2]);
            accc[3] = fmaf(wcx, f3.x, accc[3]); accr[3] = fmaf(wrx, f3.y, accr[3]);
            accc[4] = fmaf(wcx, f4.x, accc[4]); accr[4] = fmaf(wrx, f4.y, accr[4]);
            accc[5] = fmaf(wcx, f5.x, accc[5]); accr[5] = fmaf(wrx, f5.y, accr[5]);
            accc[6] = fmaf(wcx, f6.x, accc[6]); accr[6] = fmaf(wrx, f6.y, accr[6]);
            accc[7] = fmaf(wcx, f7.x, accc[7]); accr[7] = fmaf(wrx, f7.y, accr[7]);
        }
    }

    // denominators (full-warp reduce)
    #pragma unroll
    for (int o = 16; o; o >>= 1) {
        sc += __shfl_xor_sync(0xffffffffu, sc, o);
        sr += __shfl_xor_sync(0xffffffffu, sr, o);
    }
    float invc = 1.0f / sc, invr = 1.0f / sr;

    // reduce accumulators across the 8 sub-edge groups (xor 4, 8, 16)
    #pragma unroll
    for (int o = 4; o <= 16; o <<= 1) {
        #pragma unroll
        for (int j = 0; j < 8; j++) {
            accc[j] += __shfl_xor_sync(0xffffffffu, accc[j], o);
            accr[j] += __shfl_xor_sync(0xffffffffu, accr[j], o);
        }
    }
    if (eidx == 0) {   // lanes 0..3 write channels cg*8 .. cg*8+7
        float4 oc0, oc1, or0, or1;
        oc0.x = fmaxf(fmaf(accc[0], invc, bsh[cg * 8 + 0]), 0.f);
        oc0.y = fmaxf(fmaf(accc[1], invc, bsh[cg * 8 + 1]), 0.f);
        oc0.z = fmaxf(fmaf(accc[2], invc, bsh[cg * 8 + 2]), 0.f);
        oc0.w = fmaxf(fmaf(accc[3], invc, bsh[cg * 8 + 3]), 0.f);
        oc1.x = fmaxf(fmaf(accc[4], invc, bsh[cg * 8 + 4]), 0.f);
        oc1.y = fmaxf(fmaf(accc[5], invc, bsh[cg * 8 + 5]), 0.f);
        oc1.z = fmaxf(fmaf(accc[6], invc, bsh[cg * 8 + 6]), 0.f);
        oc1.w = fmaxf(fmaf(accc[7], invc, bsh[cg * 8 + 7]), 0.f);
        or0.x = fmaxf(fmaf(accr[0], invr, bsh[HID + cg * 8 + 0]), 0.f);
        or0.y = fmaxf(fmaf(accr[1], invr, bsh[HID + cg * 8 + 1]), 0.f);
        or0.z = fmaxf(fmaf(accr[2], invr, bsh[HID + cg * 8 + 2]), 0.f);
        or0.w = fmaxf(fmaf(accr[3], invr, bsh[HID + cg * 8 + 3]), 0.f);
        or1.x = fmaxf(fmaf(accr[4], invr, bsh[HID + cg * 8 + 4]), 0.f);
        or1.y = fmaxf(fmaf(accr[5], invr, bsh[HID + cg * 8 + 5]), 0.f);
        or1.z = fmaxf(fmaf(accr[6], invr, bsh[HID + cg * 8 + 6]), 0.f);
        or1.w = fmaxf(fmaf(accr[7], invr, bsh[HID + cg * 8 + 7]), 0.f);
        *(float4*)&outc[(size_t)gw * HID + cg * 8 + 0] = oc0;
        *(float4*)&outc[(size_t)gw * HID + cg * 8 + 4] = oc1;
        *(float4*)&outr[(size_t)gw * HID + cg * 8 + 0] = or0;
        *(float4*)&outr[(size_t)gw * HID + cg * 8 + 4] = or1;
    }
}

// ---------------- fused heads: sigmoid(c) and linear(r) ----------------
__global__ void __launch_bounds__(256) k_head(
    const float* __restrict__ lWc, const float* __restrict__ lbc,
    const float* __restrict__ lWr, const float* __restrict__ lbr,
    float* __restrict__ out, int n) {
    __shared__ float Wsc[HID * HID], Wsr[HID * HID];
    __shared__ float bsh[2 * HID];
    for (int i = threadIdx.x; i < HID * HID; i += blockDim.x) {
        Wsc[i] = lWc[i]; Wsr[i] = lWr[i];
    }
    if (threadIdx.x < HID) {
        bsh[threadIdx.x]       = lbc[threadIdx.x];
        bsh[HID + threadIdx.x] = lbr[threadIdx.x];
    }
    __syncthreads();
    int gw = (blockIdx.x * blockDim.x + threadIdx.x) >> 5;
    int lane = threadIdx.x & 31;
    if (gw >= n) return;
    const float* hc = g_t2c + (size_t)gw * HID;
    const float* hr = g_t2r + (size_t)gw * HID;
    float ac = bsh[lane], ar = bsh[HID + lane];
    #pragma unroll
    for (int k = 0; k < HID; k++) {
        ac = fmaf(hc[k], Wsc[k * HID + lane], ac);
        ar = fmaf(hr[k], Wsr[k * HID + lane], ar);
    }
    out[(size_t)gw * HID + lane] = 1.0f / (1.0f + __expf(-ac));
    out[(size_t)n * HID + (size_t)gw * HID + lane] = ar;
}

// ---------------- launch ----------------
extern "C" void kernel_launch(void* const* d_in, const int* in_sizes, int n_in,
                              void* d_out, int out_size) {
    const float* x = (const float*)d_in[0];
    int n = in_sizes[0] / 64;

    const int T = 256;
    long long nelem = in_sizes[1];
    int nb_scan = (n + 1023) / 1024;
    if (nelem == 2LL * EEMAX) {            // int32 [2, E]
        const int* ei = (const int*)d_in[1];
        int E = EEMAX;
        int nt8 = (E + 7) / 8;
        k_hist8<<<(nt8 + T - 1) / T, T>>>(ei + E, E, n);
        kb_scan1<<<nb_scan, 1024>>>(n);
        kb_scan2<<<1, 1024>>>(nb_scan, n);
        kb_scan3<<<nb_scan, 1024>>>(n);
        k_scatter8<<<(nt8 + T - 1) / T, T>>>(ei, ei + E, E, n);
    } else {                               // int64 [2, E] fallback
        const long long* ei = (const long long*)d_in[1];
        int E = (int)(nelem / 2);
        k_hist64<<<(E + T - 1) / T, T>>>(ei + E, E, n);
        kb_scan1<<<nb_scan, 1024>>>(n);
        kb_scan2<<<1, 1024>>>(nb_scan, n);
        kb_scan3<<<nb_scan, 1024>>>(n);
        k_scatter64<<<(E + T - 1) / T, T>>>(ei, ei + E, E, n);
    }

    // params: c at d_in[2..11], r at d_in[12..21]
    const float** c = (const float**)(d_in + 2);
    const float** r = (const float**)(d_in + 12);

    int nb = (n * 32 + T - 1) / T;  // warp per node
    k_lin1<<<nb, T>>>(x, c[0], c[1], c[2], r[0], r[1], r[2], n);
    k_agg<<<nb, T>>>(c[3], r[3], 0, n);
    k_lin2<<<nb, T>>>(c[4], c[5], c[6], r[4], r[5], r[6], n);
    k_agg<<<nb, T>>>(c[7], r[7], 1, n);
    k_head<<<nb, T>>>(c[8], c[9], r[8], r[9], (float*)d_out, n);
}

// round 10
// speedup vs baseline: 1.8043x; 1.0533x over previous
#include <cuda_runtime.h>
#include <cuda_fp16.h>

#define NN    50000
#define EEMAX 1600000
#define ETOT  (EEMAX + NN)
#define HID   32

// ---- static scratch (module zero-init; g_deg kept zero as an invariant) ----
__device__ int    g_deg[NN];
__device__ int    g_roff[NN + 1];
__device__ int    g_cur[NN];
__device__ int    g_csr[ETOT];
__device__ int    g_part[64];
__device__ int    g_part2[64];
// bank 1: layer-1 features/scores   bank 2: layer-2 (written by aggA)
__device__ __align__(16) __half2 g_lin[NN * HID];
__device__ __align__(16) __half2 g_lin2[NN * HID];
__device__ __align__(8)  float2 g_es[NN];
__device__ __align__(8)  float2 g_es2[NN];
__device__ __align__(8)  float2 g_ed[NN];
__device__ __align__(8)  float2 g_ed2[NN];

// ---------------- CSR build ----------------
__global__ void k_hist8(const int* __restrict__ dst, int E, int n) {
    int base = (blockIdx.x * blockDim.x + threadIdx.x) * 8;
    if (base + 7 < E) {
        int4 a = *(const int4*)(dst + base);
        int4 b = *(const int4*)(dst + base + 4);
        #pragma unroll
        for (int k = 0; k < 4; k++) {
            int d0 = (&a.x)[k], d1 = (&b.x)[k];
            if ((unsigned)d0 < (unsigned)n) atomicAdd(&g_deg[d0], 1);
            if ((unsigned)d1 < (unsigned)n) atomicAdd(&g_deg[d1], 1);
        }
    } else {
        for (int k = base; k < E; k++) {
            int dv = dst[k];
            if ((unsigned)dv < (unsigned)n) atomicAdd(&g_deg[dv], 1);
        }
    }
}

__global__ void k_hist64(const long long* __restrict__ dst, int E, int n) {
    int e = blockIdx.x * blockDim.x + threadIdx.x;
    if (e < E) {
        int d = (int)dst[e];
        if ((unsigned)d < (unsigned)n) atomicAdd(&g_deg[d], 1);
    }
}

__device__ __forceinline__ int warp_incl_scan(int x, int lane) {
    #pragma unroll
    for (int o = 1; o < 32; o <<= 1) {
        int y = __shfl_up_sync(0xffffffffu, x, o);
        if (lane >= o) x += y;
    }
    return x;
}

// scan pass 1: also re-zeroes g_deg (restores invariant; no memset launch)
__global__ void kb_scan1(int n) {
    __shared__ int wsum[32];
    int tid = threadIdx.x, lane = tid & 31, wid = tid >> 5;
    int i = blockIdx.x * 1024 + tid;
    int v = 0;
    if (i < n) { v = g_deg[i] + 1; g_deg[i] = 0; }   // +1 = self loop
    int x = warp_incl_scan(v, lane);
    if (lane == 31) wsum[wid] = x;
    __syncthreads();
    if (wid == 0) wsum[lane] = warp_incl_scan(wsum[lane], lane);
    __syncthreads();
    int incl = x + (wid ? wsum[wid - 1] : 0);
    if (i < n) g_roff[i] = incl - v;
    if (tid == 1023) g_part[blockIdx.x] = incl;
}

__global__ void kb_scan2(int nb, int n) {
    __shared__ int wsum[32];
    int tid = threadIdx.x, lane = tid & 31, wid = tid >> 5;
    int v = (tid < nb) ? g_part[tid] : 0;
    int x = warp_incl_scan(v, lane);
    if (lane == 31) wsum[wid] = x;
    __syncthreads();
    if (wid == 0) wsum[lane] = warp_incl_scan(wsum[lane], lane);
    __syncthreads();
    int incl = x + (wid ? wsum[wid - 1] : 0);
    if (tid < nb) g_part2[tid] = incl - v;
    if (tid == nb - 1) g_roff[n] = incl;
}

__global__ void kb_scan3(int n) {
    int i = blockIdx.x * 1024 + threadIdx.x;
    if (i < n) {
        int r = g_roff[i] + g_part2[blockIdx.x];
        g_roff[i] = r;
        g_csr[r]  = i;        // self loop in first slot
        g_cur[i]  = r + 1;
    }
}

__global__ void k_scatter8(const int* __restrict__ src,
                           const int* __restrict__ dst, int E, int n) {
    int base = (blockIdx.x * blockDim.x + threadIdx.x) * 8;
    if (base + 7 < E) {
        int4 sa = *(const int4*)(src + base);
        int4 sb = *(const int4*)(src + base + 4);
        int4 da = *(const int4*)(dst + base);
        int4 db = *(const int4*)(dst + base + 4);
        int s[8] = {sa.x, sa.y, sa.z, sa.w, sb.x, sb.y, sb.z, sb.w};
        int d[8] = {da.x, da.y, da.z, da.w, db.x, db.y, db.z, db.w};
        int p[8];
        #pragma unroll
        for (int k = 0; k < 8; k++) {
            bool ok = (unsigned)s[k] < (unsigned)n && (unsigned)d[k] < (unsigned)n;
            p[k] = ok ? atomicAdd(&g_cur[d[k]], 1) : -1;
        }
        #pragma unroll
        for (int k = 0; k < 8; k++)
            if (p[k] >= 0) g_csr[p[k]] = s[k];
    } else {
        for (int k = base; k < E; k++) {
            int s = src[k], d = dst[k];
            if ((unsigned)s < (unsigned)n && (unsigned)d < (unsigned)n) {
                int pos = atomicAdd(&g_cur[d], 1);
                g_csr[pos] = s;
            }
        }
    }
}

__global__ void k_scatter64(const long long* __restrict__ src,
                            const long long* __restrict__ dst, int E, int n) {
    int e = blockIdx.x * blockDim.x + threadIdx.x;
    if (e >= E) return;
    int s = (int)src[e], d = (int)dst[e];
    if ((unsigned)s >= (unsigned)n || (unsigned)d >= (unsigned)n) return;
    int pos = atomicAdd(&g_cur[d], 1);
    g_csr[pos] = s;
}

// ------------- fused two-branch layer-1 linear + attention coeffs -------------
__global__ void __launch_bounds__(256) k_lin1(
    const float* __restrict__ x,
    const float* __restrict__ Wc, const float* __restrict__ asc_, const float* __restrict__ adc,
    const float* __restrict__ Wr, const float* __restrict__ asr_, const float* __restrict__ adr,
    int n) {
    __shared__ float Wsc[64 * HID], Wsr[64 * HID];
    __shared__ float av[4 * HID];
    for (int i = threadIdx.x; i < 64 * HID; i += blockDim.x) {
        Wsc[i] = Wc[i]; Wsr[i] = Wr[i];
    }
    if (threadIdx.x < HID) {
        av[threadIdx.x]           = asc_[threadIdx.x];
        av[HID + threadIdx.x]     = adc[threadIdx.x];
        av[2 * HID + threadIdx.x] = asr_[threadIdx.x];
        av[3 * HID + threadIdx.x] = adr[threadIdx.x];
    }
    __syncthreads();
    int gw = (blockIdx.x * blockDim.x + threadIdx.x) >> 5;
    int lane = threadIdx.x & 31;
    if (gw >= n) return;
    const float* xr = x + (size_t)gw * 64;
    float ac = 0.f, ar = 0.f;
    #pragma unroll
    for (int k = 0; k < 64; k++) {
        float xv = xr[k];
        ac = fmaf(xv, Wsc[k * HID + lane], ac);
        ar = fmaf(xv, Wsr[k * HID + lane], ar);
    }
    g_lin[(size_t)gw * HID + lane] = __floats2half2_rn(ac, ar);
    float e0 = ac * av[lane], e1 = ac * av[HID + lane];
    float e2 = ar * av[2 * HID + lane], e3 = ar * av[3 * HID + lane];
    #pragma unroll
    for (int o = 16; o; o >>= 1) {
        e0 += __shfl_xor_sync(0xffffffffu, e0, o);
        e1 += __shfl_xor_sync(0xffffffffu, e1, o);
        e2 += __shfl_xor_sync(0xffffffffu, e2, o);
        e3 += __shfl_xor_sync(0xffffffffu, e3, o);
    }
    if (lane == 0) {
        g_es[gw] = make_float2(e0, e2);
        g_ed[gw] = make_float2(e1, e3);
    }
}

// ---------- core single-pass agg (reads the given bank) ----------
__device__ __forceinline__ void agg_core(const __half2* __restrict__ lin,
                                         const float2* __restrict__ es,
                                         const float2* __restrict__ edv,
                                         int gw, int lane,
                                         float* accc, float* accr,
                                         float& invc, float& invr) {
    int beg = g_roff[gw], end = g_roff[gw + 1];
    float2 ed = edv[gw];
    int eidx = lane >> 2;
    int cg   = lane & 3;
    float sc = 0.f, sr = 0.f;
    #pragma unroll
    for (int j = 0; j < 8; j++) { accc[j] = 0.f; accr[j] = 0.f; }

    for (int base = beg; base < end; base += 32) {
        int i = base + lane;
        int s_l = 0;
        float wc = 0.f, wr = 0.f;
        if (i < end) {
            s_l = g_csr[i];
            float2 e = es[s_l];
            float ac_ = e.x + ed.x; ac_ = (ac_ > 0.f) ? ac_ : 0.2f * ac_;
            float ar_ = e.y + ed.y; ar_ = (ar_ > 0.f) ? ar_ : 0.2f * ar_;
            wc = __expf(ac_); wr = __expf(ar_);
        }
        sc += wc; sr += wr;

        #pragma unroll
        for (int j = 0; j < 4; j++) {
            if (base + j * 8 >= end) break;             // warp-uniform
            int lsrc = j * 8 + eidx;
            float wcx = __shfl_sync(0xffffffffu, wc, lsrc);
            float wrx = __shfl_sync(0xffffffffu, wr, lsrc);
            int   s   = __shfl_sync(0xffffffffu, s_l, lsrc);
            const __half2* row = lin + (size_t)s * HID + cg * 8;
            const uint4 u0 = *(const uint4*)(row);
            const uint4 u1 = *(const uint4*)(row + 4);
            float2 f0 = __half22float2(*(const __half2*)&u0.x);
            float2 f1 = __half22float2(*(const __half2*)&u0.y);
            float2 f2 = __half22float2(*(const __half2*)&u0.z);
            float2 f3 = __half22float2(*(const __half2*)&u0.w);
            float2 f4 = __half22float2(*(const __half2*)&u1.x);
            float2 f5 = __half22float2(*(const __half2*)&u1.y);
            float2 f6 = __half22float2(*(const __half2*)&u1.z);
            float2 f7 = __half22float2(*(const __half2*)&u1.w);
            accc[0] = fmaf(wcx, f0.x, accc[0]); accr[0] = fmaf(wrx, f0.y, accr[0]);
            accc[1] = fmaf(wcx, f1.x, accc[1]); accr[1] = fmaf(wrx, f1.y, accr[1]);
            accc[2] = fmaf(wcx, f2.x, accc[2]); accr[2] = fmaf(wrx, f2.y, accr[2]);
            accc[3] = fmaf(wcx, f3.x, accc[3]); accr[3] = fmaf(wrx, f3.y, accr[3]);
            accc[4] = fmaf(wcx, f4.x, accc[4]); accr[4] = fmaf(wrx, f4.y, accr[4]);
            accc[5] = fmaf(wcx, f5.x, accc[5]); accr[5] = fmaf(wrx, f5.y, accr[5]);
            accc[6] = fmaf(wcx, f6.x, accc[6]); accr[6] = fmaf(wrx, f6.y, accr[6]);
            accc[7] = fmaf(wcx, f7.x, accc[7]); accr[7] = fmaf(wrx, f7.y, accr[7]);
        }
    }
    #pragma unroll
    for (int o = 16; o; o >>= 1) {
        sc += __shfl_xor_sync(0xffffffffu, sc, o);
        sr += __shfl_xor_sync(0xffffffffu, sr, o);
    }
    invc = 1.0f / sc; invr = 1.0f / sr;
    #pragma unroll
    for (int o = 4; o <= 16; o <<= 1) {
        #pragma unroll
        for (int j = 0; j < 8; j++) {
            accc[j] += __shfl_xor_sync(0xffffffffu, accc[j], o);
            accr[j] += __shfl_xor_sync(0xffffffffu, accr[j], o);
        }
    }
}

// ---- aggA: layer-1 agg + ReLU + layer-2 linear + layer-2 att coeffs ----
// Reads bank 1 (g_lin/g_es/g_ed), writes bank 2 -> no cross-block hazard.
__global__ void __launch_bounds__(256) k_aggA(
    const float* __restrict__ b1c, const float* __restrict__ b1r,
    const float* __restrict__ W2c, const float* __restrict__ as2c, const float* __restrict__ ad2c,
    const float* __restrict__ W2r, const float* __restrict__ as2r, const float* __restrict__ ad2r,
    int n) {
    __shared__ float Wsc[HID * HID], Wsr[HID * HID];
    __shared__ float bsh[2 * HID];
    __shared__ float av[4 * HID];
    for (int i = threadIdx.x; i < HID * HID; i += blockDim.x) {
        Wsc[i] = W2c[i]; Wsr[i] = W2r[i];
    }
    if (threadIdx.x < HID) {
        bsh[threadIdx.x]          = b1c[threadIdx.x];
        bsh[HID + threadIdx.x]    = b1r[threadIdx.x];
        av[threadIdx.x]           = as2c[threadIdx.x];
        av[HID + threadIdx.x]     = ad2c[threadIdx.x];
        av[2 * HID + threadIdx.x] = as2r[threadIdx.x];
        av[3 * HID + threadIdx.x] = ad2r[threadIdx.x];
    }
    __syncthreads();
    int gw = (blockIdx.x * blockDim.x + threadIdx.x) >> 5;
    int lane = threadIdx.x & 31;
    if (gw >= n) return;
    int cg = lane & 3;

    float accc[8], accr[8], invc, invr;
    agg_core(g_lin, g_es, g_ed, gw, lane, accc, accr, invc, invr);

    // t1 row in registers: normalize + bias + ReLU
    float hc[8], hr[8];
    #pragma unroll
    for (int j = 0; j < 8; j++) {
        hc[j] = fmaxf(fmaf(accc[j], invc, bsh[cg * 8 + j]), 0.f);
        hr[j] = fmaxf(fmaf(accr[j], invr, bsh[HID + cg * 8 + j]), 0.f);
    }
    // layer-2 linear: broadcast t1 row via shfl (channel k lives on lane k>>3,
    // register k&7), each lane -> one output channel
    float ac = 0.f, ar = 0.f;
    #pragma unroll
    for (int k = 0; k < HID; k++) {
        float tc = __shfl_sync(0xffffffffu, hc[k & 7], k >> 3);
        float tr = __shfl_sync(0xffffffffu, hr[k & 7], k >> 3);
        ac = fmaf(tc, Wsc[k * HID + lane], ac);
        ar = fmaf(tr, Wsr[k * HID + lane], ar);
    }
    g_lin2[(size_t)gw * HID + lane] = __floats2half2_rn(ac, ar);
    float e0 = ac * av[lane], e1 = ac * av[HID + lane];
    float e2 = ar * av[2 * HID + lane], e3 = ar * av[3 * HID + lane];
    #pragma unroll
    for (int o = 16; o; o >>= 1) {
        e0 += __shfl_xor_sync(0xffffffffu, e0, o);
        e1 += __shfl_xor_sync(0xffffffffu, e1, o);
        e2 += __shfl_xor_sync(0xffffffffu, e2, o);
        e3 += __shfl_xor_sync(0xffffffffu, e3, o);
    }
    if (lane == 0) {
        g_es2[gw] = make_float2(e0, e2);
        g_ed2[gw] = make_float2(e1, e3);
    }
}

// ---- aggB: layer-2 agg + ReLU + head GEMMs + sigmoid(c) -> d_out ----
__global__ void __launch_bounds__(256) k_aggB(
    const float* __restrict__ b2c, const float* __restrict__ b2r,
    const float* __restrict__ lWc, const float* __restrict__ lbc,
    const float* __restrict__ lWr, const float* __restrict__ lbr,
    float* __restrict__ out, int n) {
    __shared__ float Wsc[HID * HID], Wsr[HID * HID];
    __shared__ float bsh[2 * HID];
    __shared__ float lbsh[2 * HID];
    for (int i = threadIdx.x; i < HID * HID; i += blockDim.x) {
        Wsc[i] = lWc[i]; Wsr[i] = lWr[i];
    }
    if (threadIdx.x < HID) {
        bsh[threadIdx.x]        = b2c[threadIdx.x];
        bsh[HID + threadIdx.x]  = b2r[threadIdx.x];
        lbsh[threadIdx.x]       = lbc[threadIdx.x];
        lbsh[HID + threadIdx.x] = lbr[threadIdx.x];
    }
    __syncthreads();
    int gw = (blockIdx.x * blockDim.x + threadIdx.x) >> 5;
    int lane = threadIdx.x & 31;
    if (gw >= n) return;
    int cg = lane & 3;

    float accc[8], accr[8], invc, invr;
    agg_core(g_lin2, g_es2, g_ed2, gw, lane, accc, accr, invc, invr);

    float hc[8], hr[8];
    #pragma unroll
    for (int j = 0; j < 8; j++) {
        hc[j] = fmaxf(fmaf(accc[j], invc, bsh[cg * 8 + j]), 0.f);
        hr[j] = fmaxf(fmaf(accr[j], invr, bsh[HID + cg * 8 + j]), 0.f);
    }
    float ac = lbsh[lane], ar = lbsh[HID + lane];
    #pragma unroll
    for (int k = 0; k < HID; k++) {
        float tc = __shfl_sync(0xffffffffu, hc[k & 7], k >> 3);
        float tr = __shfl_sync(0xffffffffu, hr[k & 7], k >> 3);
        ac = fmaf(tc, Wsc[k * HID + lane], ac);
        ar = fmaf(tr, Wsr[k * HID + lane], ar);
    }
    out[(size_t)gw * HID + lane] = 1.0f / (1.0f + __expf(-ac));
    out[(size_t)n * HID + (size_t)gw * HID + lane] = ar;
}

// ---------------- launch ----------------
extern "C" void kernel_launch(void* const* d_in, const int* in_sizes, int n_in,
                              void* d_out, int out_size) {
    const float* x = (const float*)d_in[0];
    int n = in_sizes[0] / 64;

    const int T = 256;
    long long nelem = in_sizes[1];
    int nb_scan = (n + 1023) / 1024;
    if (nelem == 2LL * EEMAX) {            // int32 [2, E]
        const int* ei = (const int*)d_in[1];
        int E = EEMAX;
        int nt8 = (E + 7) / 8;
        k_hist8<<<(nt8 + T - 1) / T, T>>>(ei + E, E, n);
        kb_scan1<<<nb_scan, 1024>>>(n);
        kb_scan2<<<1, 1024>>>(nb_scan, n);
        kb_scan3<<<nb_scan, 1024>>>(n);
        k_scatter8<<<(nt8 + T - 1) / T, T>>>(ei, ei + E, E, n);
    } else {                               // int64 [2, E] fallback
        const long long* ei = (const long long*)d_in[1];
        int E = (int)(nelem / 2);
        k_hist64<<<(E + T - 1) / T, T>>>(ei + E, E, n);
        kb_scan1<<<nb_scan, 1024>>>(n);
        kb_scan2<<<1, 1024>>>(nb_scan, n);
        kb_scan3<<<nb_scan, 1024>>>(n);
        k_scatter64<<<(E + T - 1) / T, T>>>(ei, ei + E, E, n);
    }

    // params: c at d_in[2..11], r at d_in[12..21]
    const float** c = (const float**)(d_in + 2);
    const float** r = (const float**)(d_in + 12);

    int nb = (n * 32 + T - 1) / T;  // warp per node
    k_lin1<<<nb, T>>>(x, c[0], c[1], c[2], r[0], r[1], r[2], n);
    k_aggA<<<nb, T>>>(c[3], r[3], c[4], c[5], c[6], r[4], r[5], r[6], n);
    k_aggB<<<nb, T>>>(c[7], r[7], c[8], c[9], r[8], r[9], (float*)d_out, n);
}

// round 11
// speedup vs baseline: 1.8541x; 1.0276x over previous
#include <cuda_runtime.h>
#include <cuda_fp16.h>

#define NN    50000
#define EEMAX 1600000
#define ETOT  (EEMAX + NN)
#define HID   32

// ---- static scratch (module zero-init; g_deg kept zero as an invariant) ----
__device__ int    g_deg[NN];
__device__ int    g_roff[NN + 1];
__device__ int    g_cur[NN];
__device__ int    g_csr[ETOT];
__device__ int    g_part[64];
// bank 1: layer-1 features/scores   bank 2: layer-2 (written by aggA)
__device__ __align__(16) __half2 g_lin[NN * HID];
__device__ __align__(16) __half2 g_lin2[NN * HID];
__device__ __align__(8)  float2 g_es[NN];
__device__ __align__(8)  float2 g_es2[NN];
__device__ __align__(8)  float2 g_ed[NN];
__device__ __align__(8)  float2 g_ed2[NN];

// ---------------- fused front: lin1 blocks + hist blocks ----------------
// Blocks [0, nb_lin): two-branch layer-1 linear + attention coefficients.
// Blocks [nb_lin, nb_lin+nb_hist): 8-wide degree histogram (independent work,
// overlapped in one launch).
__global__ void __launch_bounds__(256) k_front(
    const float* __restrict__ x,
    const float* __restrict__ Wc, const float* __restrict__ asc_, const float* __restrict__ adc,
    const float* __restrict__ Wr, const float* __restrict__ asr_, const float* __restrict__ adr,
    const int* __restrict__ dst, int E, int n, int nb_lin) {
    if (blockIdx.x >= (unsigned)nb_lin) {
        // ---- histogram path ----
        int hb = blockIdx.x - nb_lin;
        int base = (hb * blockDim.x + threadIdx.x) * 8;
        if (base + 7 < E) {
            int4 a = *(const int4*)(dst + base);
            int4 b = *(const int4*)(dst + base + 4);
            #pragma unroll
            for (int k = 0; k < 4; k++) {
                int d0 = (&a.x)[k], d1 = (&b.x)[k];
                if ((unsigned)d0 < (unsigned)n) atomicAdd(&g_deg[d0], 1);
                if ((unsigned)d1 < (unsigned)n) atomicAdd(&g_deg[d1], 1);
            }
        } else {
            for (int k = base; k < E; k++) {
                int dv = dst[k];
                if ((unsigned)dv < (unsigned)n) atomicAdd(&g_deg[dv], 1);
            }
        }
        return;
    }
    // ---- lin1 path ----
    __shared__ float Wsc[64 * HID], Wsr[64 * HID];
    __shared__ float av[4 * HID];
    for (int i = threadIdx.x; i < 64 * HID; i += blockDim.x) {
        Wsc[i] = Wc[i]; Wsr[i] = Wr[i];
    }
    if (threadIdx.x < HID) {
        av[threadIdx.x]           = asc_[threadIdx.x];
        av[HID + threadIdx.x]     = adc[threadIdx.x];
        av[2 * HID + threadIdx.x] = asr_[threadIdx.x];
        av[3 * HID + threadIdx.x] = adr[threadIdx.x];
    }
    __syncthreads();
    int gw = (blockIdx.x * blockDim.x + threadIdx.x) >> 5;
    int lane = threadIdx.x & 31;
    if (gw >= n) return;
    const float* xr = x + (size_t)gw * 64;
    float ac = 0.f, ar = 0.f;
    #pragma unroll
    for (int k = 0; k < 64; k++) {
        float xv = xr[k];
        ac = fmaf(xv, Wsc[k * HID + lane], ac);
        ar = fmaf(xv, Wsr[k * HID + lane], ar);
    }
    g_lin[(size_t)gw * HID + lane] = __floats2half2_rn(ac, ar);
    float e0 = ac * av[lane], e1 = ac * av[HID + lane];
    float e2 = ar * av[2 * HID + lane], e3 = ar * av[3 * HID + lane];
    #pragma unroll
    for (int o = 16; o; o >>= 1) {
        e0 += __shfl_xor_sync(0xffffffffu, e0, o);
        e1 += __shfl_xor_sync(0xffffffffu, e1, o);
        e2 += __shfl_xor_sync(0xffffffffu, e2, o);
        e3 += __shfl_xor_sync(0xffffffffu, e3, o);
    }
    if (lane == 0) {
        g_es[gw] = make_float2(e0, e2);
        g_ed[gw] = make_float2(e1, e3);
    }
}

__global__ void k_hist64(const long long* __restrict__ dst, int E, int n) {
    int e = blockIdx.x * blockDim.x + threadIdx.x;
    if (e < E) {
        int d = (int)dst[e];
        if ((unsigned)d < (unsigned)n) atomicAdd(&g_deg[d], 1);
    }
}

__device__ __forceinline__ int warp_incl_scan(int x, int lane) {
    #pragma unroll
    for (int o = 1; o < 32; o <<= 1) {
        int y = __shfl_up_sync(0xffffffffu, x, o);
        if (lane >= o) x += y;
    }
    return x;
}

// scan pass 1: also re-zeroes g_deg (restores invariant; no memset launch)
__global__ void kb_scan1(int n) {
    __shared__ int wsum[32];
    int tid = threadIdx.x, lane = tid & 31, wid = tid >> 5;
    int i = blockIdx.x * 1024 + tid;
    int v = 0;
    if (i < n) { v = g_deg[i] + 1; g_deg[i] = 0; }   // +1 = self loop
    int x = warp_incl_scan(v, lane);
    if (lane == 31) wsum[wid] = x;
    __syncthreads();
    if (wid == 0) wsum[lane] = warp_incl_scan(wsum[lane], lane);
    __syncthreads();
    int incl = x + (wid ? wsum[wid - 1] : 0);
    if (i < n) g_roff[i] = incl - v;
    if (tid == 1023) g_part[blockIdx.x] = incl;
}

// scan2+scan3 merged: every block redundantly scans the <=64 partials in
// smem, then applies its offset + self-loop placement.
__global__ void kb_scan23(int nbp, int n) {
    __shared__ int ps[64];
    int tid = threadIdx.x;
    if (tid < 64) ps[tid] = (tid < nbp) ? g_part[tid] : 0;
    __syncthreads();
    #pragma unroll
    for (int o = 1; o < 64; o <<= 1) {
        int v = 0, add = 0;
        if (tid < 64) { v = ps[tid]; add = (tid >= o) ? ps[tid - o] : 0; }
        __syncthreads();
        if (tid < 64) ps[tid] = v + add;
        __syncthreads();
    }
    int off = (blockIdx.x > 0) ? ps[blockIdx.x - 1] : 0;
    int i = blockIdx.x * 1024 + tid;
    if (i < n) {
        int r = g_roff[i] + off;
        g_roff[i] = r;
        g_csr[r]  = i;        // self loop in first slot
        g_cur[i]  = r + 1;
    }
    if (blockIdx.x == 0 && tid == 0) g_roff[n] = ps[nbp - 1];
}

__global__ void k_scatter8(const int* __restrict__ src,
                           const int* __restrict__ dst, int E, int n) {
    int base = (blockIdx.x * blockDim.x + threadIdx.x) * 8;
    if (base + 7 < E) {
        int4 sa = *(const int4*)(src + base);
        int4 sb = *(const int4*)(src + base + 4);
        int4 da = *(const int4*)(dst + base);
        int4 db = *(const int4*)(dst + base + 4);
        int s[8] = {sa.x, sa.y, sa.z, sa.w, sb.x, sb.y, sb.z, sb.w};
        int d[8] = {da.x, da.y, da.z, da.w, db.x, db.y, db.z, db.w};
        int p[8];
        #pragma unroll
        for (int k = 0; k < 8; k++) {
            bool ok = (unsigned)s[k] < (unsigned)n && (unsigned)d[k] < (unsigned)n;
            p[k] = ok ? atomicAdd(&g_cur[d[k]], 1) : -1;
        }
        #pragma unroll
        for (int k = 0; k < 8; k++)
            if (p[k] >= 0) g_csr[p[k]] = s[k];
    } else {
        for (int k = base; k < E; k++) {
            int s = src[k], d = dst[k];
            if ((unsigned)s < (unsigned)n && (unsigned)d < (unsigned)n) {
                int pos = atomicAdd(&g_cur[d], 1);
                g_csr[pos] = s;
            }
        }
    }
}

__global__ void k_scatter64(const long long* __restrict__ src,
                            const long long* __restrict__ dst, int E, int n) {
    int e = blockIdx.x * blockDim.x + threadIdx.x;
    if (e >= E) return;
    int s = (int)src[e], d = (int)dst[e];
    if ((unsigned)s >= (unsigned)n || (unsigned)d >= (unsigned)n) return;
    int pos = atomicAdd(&g_cur[d], 1);
    g_csr[pos] = s;
}

// int64 fallback lin1 (separate, unfused)
__global__ void __launch_bounds__(256) k_lin1_only(
    const float* __restrict__ x,
    const float* __restrict__ Wc, const float* __restrict__ asc_, const float* __restrict__ adc,
    const float* __restrict__ Wr, const float* __restrict__ asr_, const float* __restrict__ adr,
    int n) {
    __shared__ float Wsc[64 * HID], Wsr[64 * HID];
    __shared__ float av[4 * HID];
    for (int i = threadIdx.x; i < 64 * HID; i += blockDim.x) {
        Wsc[i] = Wc[i]; Wsr[i] = Wr[i];
    }
    if (threadIdx.x < HID) {
        av[threadIdx.x]           = asc_[threadIdx.x];
        av[HID + threadIdx.x]     = adc[threadIdx.x];
        av[2 * HID + threadIdx.x] = asr_[threadIdx.x];
        av[3 * HID + threadIdx.x] = adr[threadIdx.x];
    }
    __syncthreads();
    int gw = (blockIdx.x * blockDim.x + threadIdx.x) >> 5;
    int lane = threadIdx.x & 31;
    if (gw >= n) return;
    const float* xr = x + (size_t)gw * 64;
    float ac = 0.f, ar = 0.f;
    #pragma unroll
    for (int k = 0; k < 64; k++) {
        float xv = xr[k];
        ac = fmaf(xv, Wsc[k * HID + lane], ac);
        ar = fmaf(xv, Wsr[k * HID + lane], ar);
    }
    g_lin[(size_t)gw * HID + lane] = __floats2half2_rn(ac, ar);
    float e0 = ac * av[lane], e1 = ac * av[HID + lane];
    float e2 = ar * av[2 * HID + lane], e3 = ar * av[3 * HID + lane];
    #pragma unroll
    for (int o = 16; o; o >>= 1) {
        e0 += __shfl_xor_sync(0xffffffffu, e0, o);
        e1 += __shfl_xor_sync(0xffffffffu, e1, o);
        e2 += __shfl_xor_sync(0xffffffffu, e2, o);
        e3 += __shfl_xor_sync(0xffffffffu, e3, o);
    }
    if (lane == 0) {
        g_es[gw] = make_float2(e0, e2);
        g_ed[gw] = make_float2(e1, e3);
    }
}

// ---------- core single-pass agg (reads the given bank) ----------
__device__ __forceinline__ void agg_core(const __half2* __restrict__ lin,
                                         const float2* __restrict__ es,
                                         const float2* __restrict__ edv,
                                         int gw, int lane,
                                         float* accc, float* accr,
                                         float& invc, float& invr) {
    int beg = g_roff[gw], end = g_roff[gw + 1];
    float2 ed = edv[gw];
    int eidx = lane >> 2;
    int cg   = lane & 3;
    float sc = 0.f, sr = 0.f;
    #pragma unroll
    for (int j = 0; j < 8; j++) { accc[j] = 0.f; accr[j] = 0.f; }

    for (int base = beg; base < end; base += 32) {
        int i = base + lane;
        int s_l = 0;
        float wc = 0.f, wr = 0.f;
        if (i < end) {
            s_l = g_csr[i];
            float2 e = es[s_l];
            float ac_ = e.x + ed.x; ac_ = (ac_ > 0.f) ? ac_ : 0.2f * ac_;
            float ar_ = e.y + ed.y; ar_ = (ar_ > 0.f) ? ar_ : 0.2f * ar_;
            wc = __expf(ac_); wr = __expf(ar_);
        }
        sc += wc; sr += wr;

        #pragma unroll
        for (int j = 0; j < 4; j++) {
            if (base + j * 8 >= end) break;             // warp-uniform
            int lsrc = j * 8 + eidx;
            float wcx = __shfl_sync(0xffffffffu, wc, lsrc);
            float wrx = __shfl_sync(0xffffffffu, wr, lsrc);
            int   s   = __shfl_sync(0xffffffffu, s_l, lsrc);
            const __half2* row = lin + (size_t)s * HID + cg * 8;
            const uint4 u0 = *(const uint4*)(row);
            const uint4 u1 = *(const uint4*)(row + 4);
            float2 f0 = __half22float2(*(const __half2*)&u0.x);
            float2 f1 = __half22float2(*(const __half2*)&u0.y);
            float2 f2 = __half22float2(*(const __half2*)&u0.z);
            float2 f3 = __half22float2(*(const __half2*)&u0.w);
            float2 f4 = __half22float2(*(const __half2*)&u1.x);
            float2 f5 = __half22float2(*(const __half2*)&u1.y);
            float2 f6 = __half22float2(*(const __half2*)&u1.z);
            float2 f7 = __half22float2(*(const __half2*)&u1.w);
            accc[0] = fmaf(wcx, f0.x, accc[0]); accr[0] = fmaf(wrx, f0.y, accr[0]);
            accc[1] = fmaf(wcx, f1.x, accc[1]); accr[1] = fmaf(wrx, f1.y, accr[1]);
            accc[2] = fmaf(wcx, f2.x, accc[2]); accr[2] = fmaf(wrx, f2.y, accr[2]);
            accc[3] = fmaf(wcx, f3.x, accc[3]); accr[3] = fmaf(wrx, f3.y, accr[3]);
            accc[4] = fmaf(wcx, f4.x, accc[4]); accr[4] = fmaf(wrx, f4.y, accr[4]);
            accc[5] = fmaf(wcx, f5.x, accc[5]); accr[5] = fmaf(wrx, f5.y, accr[5]);
            accc[6] = fmaf(wcx, f6.x, accc[6]); accr[6] = fmaf(wrx, f6.y, accr[6]);
            accc[7] = fmaf(wcx, f7.x, accc[7]); accr[7] = fmaf(wrx, f7.y, accr[7]);
        }
    }
    #pragma unroll
    for (int o = 16; o; o >>= 1) {
        sc += __shfl_xor_sync(0xffffffffu, sc, o);
        sr += __shfl_xor_sync(0xffffffffu, sr, o);
    }
    invc = 1.0f / sc; invr = 1.0f / sr;
    #pragma unroll
    for (int o = 4; o <= 16; o <<= 1) {
        #pragma unroll
        for (int j = 0; j < 8; j++) {
            accc[j] += __shfl_xor_sync(0xffffffffu, accc[j], o);
            accr[j] += __shfl_xor_sync(0xffffffffu, accr[j], o);
        }
    }
}

// ---- aggA: layer-1 agg + ReLU + layer-2 linear + layer-2 att coeffs ----
__global__ void __launch_bounds__(256) k_aggA(
    const float* __restrict__ b1c, const float* __restrict__ b1r,
    const float* __restrict__ W2c, const float* __restrict__ as2c, const float* __restrict__ ad2c,
    const float* __restrict__ W2r, const float* __restrict__ as2r, const float* __restrict__ ad2r,
    int n) {
    __shared__ float Wsc[HID * HID], Wsr[HID * HID];
    __shared__ float bsh[2 * HID];
    __shared__ float av[4 * HID];
    for (int i = threadIdx.x; i < HID * HID; i += blockDim.x) {
        Wsc[i] = W2c[i]; Wsr[i] = W2r[i];
    }
    if (threadIdx.x < HID) {
        bsh[threadIdx.x]          = b1c[threadIdx.x];
        bsh[HID + threadIdx.x]    = b1r[threadIdx.x];
        av[threadIdx.x]           = as2c[threadIdx.x];
        av[HID + threadIdx.x]     = ad2c[threadIdx.x];
        av[2 * HID + threadIdx.x] = as2r[threadIdx.x];
        av[3 * HID + threadIdx.x] = ad2r[threadIdx.x];
    }
    __syncthreads();
    int gw = (blockIdx.x * blockDim.x + threadIdx.x) >> 5;
    int lane = threadIdx.x & 31;
    if (gw >= n) return;
    int cg = lane & 3;

    float accc[8], accr[8], invc, invr;
    agg_core(g_lin, g_es, g_ed, gw, lane, accc, accr, invc, invr);

    float hc[8], hr[8];
    #pragma unroll
    for (int j = 0; j < 8; j++) {
        hc[j] = fmaxf(fmaf(accc[j], invc, bsh[cg * 8 + j]), 0.f);
        hr[j] = fmaxf(fmaf(accr[j], invr, bsh[HID + cg * 8 + j]), 0.f);
    }
    // layer-2 linear: channel k lives on lane k>>3, register k&7
    float ac = 0.f, ar = 0.f;
    #pragma unroll
    for (int k = 0; k < HID; k++) {
        float tc = __shfl_sync(0xffffffffu, hc[k & 7], k >> 3);
        float tr = __shfl_sync(0xffffffffu, hr[k & 7], k >> 3);
        ac = fmaf(tc, Wsc[k * HID + lane], ac);
        ar = fmaf(tr, Wsr[k * HID + lane], ar);
    }
    g_lin2[(size_t)gw * HID + lane] = __floats2half2_rn(ac, ar);
    float e0 = ac * av[lane], e1 = ac * av[HID + lane];
    float e2 = ar * av[2 * HID + lane], e3 = ar * av[3 * HID + lane];
    #pragma unroll
    for (int o = 16; o; o >>= 1) {
        e0 += __shfl_xor_sync(0xffffffffu, e0, o);
        e1 += __shfl_xor_sync(0xffffffffu, e1, o);
        e2 += __shfl_xor_sync(0xffffffffu, e2, o);
        e3 += __shfl_xor_sync(0xffffffffu, e3, o);
    }
    if (lane == 0) {
        g_es2[gw] = make_float2(e0, e2);
        g_ed2[gw] = make_float2(e1, e3);
    }
}

// ---- aggB: layer-2 agg + ReLU + head GEMMs + sigmoid(c) -> d_out ----
__global__ void __launch_bounds__(256) k_aggB(
    const float* __restrict__ b2c, const float* __restrict__ b2r,
    const float* __restrict__ lWc, const float* __restrict__ lbc,
    const float* __restrict__ lWr, const float* __restrict__ lbr,
    float* __restrict__ out, int n) {
    __shared__ float Wsc[HID * HID], Wsr[HID * HID];
    __shared__ float bsh[2 * HID];
    __shared__ float lbsh[2 * HID];
    for (int i = threadIdx.x; i < HID * HID; i += blockDim.x) {
        Wsc[i] = lWc[i]; Wsr[i] = lWr[i];
    }
    if (threadIdx.x < HID) {
        bsh[threadIdx.x]        = b2c[threadIdx.x];
        bsh[HID + threadIdx.x]  = b2r[threadIdx.x];
        lbsh[threadIdx.x]       = lbc[threadIdx.x];
        lbsh[HID + threadIdx.x] = lbr[threadIdx.x];
    }
    __syncthreads();
    int gw = (blockIdx.x * blockDim.x + threadIdx.x) >> 5;
    int lane = threadIdx.x & 31;
    if (gw >= n) return;
    int cg = lane & 3;

    float accc[8], accr[8], invc, invr;
    agg_core(g_lin2, g_es2, g_ed2, gw, lane, accc, accr, invc, invr);

    float hc[8], hr[8];
    #pragma unroll
    for (int j = 0; j < 8; j++) {
        hc[j] = fmaxf(fmaf(accc[j], invc, bsh[cg * 8 + j]), 0.f);
        hr[j] = fmaxf(fmaf(accr[j], invr, bsh[HID + cg * 8 + j]), 0.f);
    }
    float ac = lbsh[lane], ar = lbsh[HID + lane];
    #pragma unroll
    for (int k = 0; k < HID; k++) {
        float tc = __shfl_sync(0xffffffffu, hc[k & 7], k >> 3);
        float tr = __shfl_sync(0xffffffffu, hr[k & 7], k >> 3);
        ac = fmaf(tc, Wsc[k * HID + lane], ac);
        ar = fmaf(tr, Wsr[k * HID + lane], ar);
    }
    out[(size_t)gw * HID + lane] = 1.0f / (1.0f + __expf(-ac));
    out[(size_t)n * HID + (size_t)gw * HID + lane] = ar;
}

// ---------------- launch ----------------
extern "C" void kernel_launch(void* const* d_in, const int* in_sizes, int n_in,
                              void* d_out, int out_size) {
    const float* x = (const float*)d_in[0];
    int n = in_sizes[0] / 64;

    // params: c at d_in[2..11], r at d_in[12..21]
    const float** c = (const float**)(d_in + 2);
    const float** r = (const float**)(d_in + 12);

    const int T = 256;
    long long nelem = in_sizes[1];
    int nb_scan = (n + 1023) / 1024;
    int nb = (n * 32 + T - 1) / T;  // warp per node

    if (nelem == 2LL * EEMAX) {            // int32 [2, E]
        const int* ei = (const int*)d_in[1];
        int E = EEMAX;
        int nt8 = (E + 7) / 8;
        int nb_hist = (nt8 + T - 1) / T;
        // lin1 and hist fused: overlap independent work
        k_front<<<nb + nb_hist, T>>>(x, c[0], c[1], c[2], r[0], r[1], r[2],
                                     ei + E, E, n, nb);
        kb_scan1<<<nb_scan, 1024>>>(n);
        kb_scan23<<<nb_scan, 1024>>>(nb_scan, n);
        k_scatter8<<<nb_hist, T>>>(ei, ei + E, E, n);
    } else {                               // int64 [2, E] fallback
        const long long* ei = (const long long*)d_in[1];
        int E = (int)(nelem / 2);
        k_lin1_only<<<nb, T>>>(x, c[0], c[1], c[2], r[0], r[1], r[2], n);
        k_hist64<<<(E + T - 1) / T, T>>>(ei + E, E, n);
        kb_scan1<<<nb_scan, 1024>>>(n);
        kb_scan23<<<nb_scan, 1024>>>(nb_scan, n);
        k_scatter64<<<(E + T - 1) / T, T>>>(ei, ei + E, E, n);
    }

    k_aggA<<<nb, T>>>(c[3], r[3], c[4], c[5], c[6], r[4], r[5], r[6], n);
    k_aggB<<<nb, T>>>(c[7], r[7], c[8], c[9], r[8], r[9], (float*)d_out, n);
}

// round 12
// speedup vs baseline: 1.8712x; 1.0092x over previous
#include <cuda_runtime.h>
#include <cuda_fp16.h>

#define NN    50000
#define EEMAX 1600000
#define ETOT  (EEMAX + NN)
#define HID   32

// ---- static scratch (module zero-init; g_deg kept zero as an invariant) ----
__device__ int    g_deg[NN];
__device__ int    g_roff[NN + 1];
__device__ int    g_cur[NN];
__device__ int    g_rank[EEMAX];
__device__ int    g_csr[ETOT];
__device__ int    g_part[64];
// bank 1: layer-1 features/scores   bank 2: layer-2 (written by aggA)
__device__ __align__(16) __half2 g_lin[NN * HID];
__device__ __align__(16) __half2 g_lin2[NN * HID];
__device__ __align__(8)  float2 g_es[NN];
__device__ __align__(8)  float2 g_es2[NN];
__device__ __align__(8)  float2 g_ed[NN];
__device__ __align__(8)  float2 g_ed2[NN];

// ---------------- fused front: lin1 blocks + hist blocks ----------------
// Hist path now KEEPS the atomicAdd return value = rank of edge within its
// dst bucket -> scatter needs no atomics at all.
__global__ void __launch_bounds__(256) k_front(
    const float* __restrict__ x,
    const float* __restrict__ Wc, const float* __restrict__ asc_, const float* __restrict__ adc,
    const float* __restrict__ Wr, const float* __restrict__ asr_, const float* __restrict__ adr,
    const int* __restrict__ dst, int E, int n, int nb_lin) {
    if (blockIdx.x >= (unsigned)nb_lin) {
        // ---- histogram + rank path ----
        int hb = blockIdx.x - nb_lin;
        int base = (hb * blockDim.x + threadIdx.x) * 8;
        if (base + 7 < E) {
            int4 a = *(const int4*)(dst + base);
            int4 b = *(const int4*)(dst + base + 4);
            int d[8] = {a.x, a.y, a.z, a.w, b.x, b.y, b.z, b.w};
            int rk[8];
            #pragma unroll
            for (int k = 0; k < 8; k++) {
                bool ok = (unsigned)d[k] < (unsigned)n;
                rk[k] = ok ? atomicAdd(&g_deg[d[k]], 1) : -1;
            }
            *(int4*)(g_rank + base)     = make_int4(rk[0], rk[1], rk[2], rk[3]);
            *(int4*)(g_rank + base + 4) = make_int4(rk[4], rk[5], rk[6], rk[7]);
        } else {
            for (int k = base; k < E; k++) {
                int dv = dst[k];
                g_rank[k] = ((unsigned)dv < (unsigned)n)
                            ? atomicAdd(&g_deg[dv], 1) : -1;
            }
        }
        return;
    }
    // ---- lin1 path ----
    __shared__ float Wsc[64 * HID], Wsr[64 * HID];
    __shared__ float av[4 * HID];
    for (int i = threadIdx.x; i < 64 * HID; i += blockDim.x) {
        Wsc[i] = Wc[i]; Wsr[i] = Wr[i];
    }
    if (threadIdx.x < HID) {
        av[threadIdx.x]           = asc_[threadIdx.x];
        av[HID + threadIdx.x]     = adc[threadIdx.x];
        av[2 * HID + threadIdx.x] = asr_[threadIdx.x];
        av[3 * HID + threadIdx.x] = adr[threadIdx.x];
    }
    __syncthreads();
    int gw = (blockIdx.x * blockDim.x + threadIdx.x) >> 5;
    int lane = threadIdx.x & 31;
    if (gw >= n) return;
    const float* xr = x + (size_t)gw * 64;
    float ac = 0.f, ar = 0.f;
    #pragma unroll
    for (int k = 0; k < 64; k++) {
        float xv = xr[k];
        ac = fmaf(xv, Wsc[k * HID + lane], ac);
        ar = fmaf(xv, Wsr[k * HID + lane], ar);
    }
    g_lin[(size_t)gw * HID + lane] = __floats2half2_rn(ac, ar);
    float e0 = ac * av[lane], e1 = ac * av[HID + lane];
    float e2 = ar * av[2 * HID + lane], e3 = ar * av[3 * HID + lane];
    #pragma unroll
    for (int o = 16; o; o >>= 1) {
        e0 += __shfl_xor_sync(0xffffffffu, e0, o);
        e1 += __shfl_xor_sync(0xffffffffu, e1, o);
        e2 += __shfl_xor_sync(0xffffffffu, e2, o);
        e3 += __shfl_xor_sync(0xffffffffu, e3, o);
    }
    if (lane == 0) {
        g_es[gw] = make_float2(e0, e2);
        g_ed[gw] = make_float2(e1, e3);
    }
}

__global__ void k_hist64(const long long* __restrict__ dst, int E, int n) {
    int e = blockIdx.x * blockDim.x + threadIdx.x;
    if (e < E) {
        int d = (int)dst[e];
        if ((unsigned)d < (unsigned)n) atomicAdd(&g_deg[d], 1);
    }
}

__device__ __forceinline__ int warp_incl_scan(int x, int lane) {
    #pragma unroll
    for (int o = 1; o < 32; o <<= 1) {
        int y = __shfl_up_sync(0xffffffffu, x, o);
        if (lane >= o) x += y;
    }
    return x;
}

// scan pass 1: also re-zeroes g_deg (restores invariant; no memset launch)
__global__ void kb_scan1(int n) {
    __shared__ int wsum[32];
    int tid = threadIdx.x, lane = tid & 31, wid = tid >> 5;
    int i = blockIdx.x * 1024 + tid;
    int v = 0;
    if (i < n) { v = g_deg[i] + 1; g_deg[i] = 0; }   // +1 = self loop
    int x = warp_incl_scan(v, lane);
    if (lane == 31) wsum[wid] = x;
    __syncthreads();
    if (wid == 0) wsum[lane] = warp_incl_scan(wsum[lane], lane);
    __syncthreads();
    int incl = x + (wid ? wsum[wid - 1] : 0);
    if (i < n) g_roff[i] = incl - v;
    if (tid == 1023) g_part[blockIdx.x] = incl;
}

// scan2+scan3 merged: every block redundantly scans the <=64 partials in
// smem, then applies its offset + self-loop placement.
__global__ void kb_scan23(int nbp, int n) {
    __shared__ int ps[64];
    int tid = threadIdx.x;
    if (tid < 64) ps[tid] = (tid < nbp) ? g_part[tid] : 0;
    __syncthreads();
    #pragma unroll
    for (int o = 1; o < 64; o <<= 1) {
        int v = 0, add = 0;
        if (tid < 64) { v = ps[tid]; add = (tid >= o) ? ps[tid - o] : 0; }
        __syncthreads();
        if (tid < 64) ps[tid] = v + add;
        __syncthreads();
    }
    int off = (blockIdx.x > 0) ? ps[blockIdx.x - 1] : 0;
    int i = blockIdx.x * 1024 + tid;
    if (i < n) {
        int r = g_roff[i] + off;
        g_roff[i] = r;
        g_csr[r]  = i;        // self loop in first slot
        g_cur[i]  = r + 1;    // (used by int64 fallback scatter only)
    }
    if (blockIdx.x == 0 && tid == 0) g_roff[n] = ps[nbp - 1];
}

// atomic-free scatter: pos = roff[d] + 1 + rank (rank from hist pass)
__global__ void k_scatter8(const int* __restrict__ src,
                           const int* __restrict__ dst, int E, int n) {
    int base = (blockIdx.x * blockDim.x + threadIdx.x) * 8;
    if (base + 7 < E) {
        int4 sa = *(const int4*)(src + base);
        int4 sb = *(const int4*)(src + base + 4);
        int4 da = *(const int4*)(dst + base);
        int4 db = *(const int4*)(dst + base + 4);
        int4 ra = *(const int4*)(g_rank + base);
        int4 rb = *(const int4*)(g_rank + base + 4);
        int s[8] = {sa.x, sa.y, sa.z, sa.w, sb.x, sb.y, sb.z, sb.w};
        int d[8] = {da.x, da.y, da.z, da.w, db.x, db.y, db.z, db.w};
        int rk[8] = {ra.x, ra.y, ra.z, ra.w, rb.x, rb.y, rb.z, rb.w};
        int pos[8];
        #pragma unroll
        for (int k = 0; k < 8; k++)
            pos[k] = (rk[k] >= 0) ? (g_roff[d[k]] + 1 + rk[k]) : -1;
        #pragma unroll
        for (int k = 0; k < 8; k++)
            if (pos[k] >= 0) g_csr[pos[k]] = s[k];
    } else {
        for (int k = base; k < E; k++) {
            int rk = g_rank[k];
            if (rk >= 0) {
                int s = src[k], d = dst[k];
                if ((unsigned)s < (unsigned)n)
                    g_csr[g_roff[d] + 1 + rk] = s;
            }
        }
    }
}

__global__ void k_scatter64(const long long* __restrict__ src,
                            const long long* __restrict__ dst, int E, int n) {
    int e = blockIdx.x * blockDim.x + threadIdx.x;
    if (e >= E) return;
    int s = (int)src[e], d = (int)dst[e];
    if ((unsigned)s >= (unsigned)n || (unsigned)d >= (unsigned)n) return;
    int pos = atomicAdd(&g_cur[d], 1);
    g_csr[pos] = s;
}

// int64 fallback lin1 (separate, unfused)
__global__ void __launch_bounds__(256) k_lin1_only(
    const float* __restrict__ x,
    const float* __restrict__ Wc, const float* __restrict__ asc_, const float* __restrict__ adc,
    const float* __restrict__ Wr, const float* __restrict__ asr_, const float* __restrict__ adr,
    int n) {
    __shared__ float Wsc[64 * HID], Wsr[64 * HID];
    __shared__ float av[4 * HID];
    for (int i = threadIdx.x; i < 64 * HID; i += blockDim.x) {
        Wsc[i] = Wc[i]; Wsr[i] = Wr[i];
    }
    if (threadIdx.x < HID) {
        av[threadIdx.x]           = asc_[threadIdx.x];
        av[HID + threadIdx.x]     = adc[threadIdx.x];
        av[2 * HID + threadIdx.x] = asr_[threadIdx.x];
        av[3 * HID + threadIdx.x] = adr[threadIdx.x];
    }
    __syncthreads();
    int gw = (blockIdx.x * blockDim.x + threadIdx.x) >> 5;
    int lane = threadIdx.x & 31;
    if (gw >= n) return;
    const float* xr = x + (size_t)gw * 64;
    float ac = 0.f, ar = 0.f;
    #pragma unroll
    for (int k = 0; k < 64; k++) {
        float xv = xr[k];
        ac = fmaf(xv, Wsc[k * HID + lane], ac);
        ar = fmaf(xv, Wsr[k * HID + lane], ar);
    }
    g_lin[(size_t)gw * HID + lane] = __floats2half2_rn(ac, ar);
    float e0 = ac * av[lane], e1 = ac * av[HID + lane];
    float e2 = ar * av[2 * HID + lane], e3 = ar * av[3 * HID + lane];
    #pragma unroll
    for (int o = 16; o; o >>= 1) {
        e0 += __shfl_xor_sync(0xffffffffu, e0, o);
        e1 += __shfl_xor_sync(0xffffffffu, e1, o);
        e2 += __shfl_xor_sync(0xffffffffu, e2, o);
        e3 += __shfl_xor_sync(0xffffffffu, e3, o);
    }
    if (lane == 0) {
        g_es[gw] = make_float2(e0, e2);
        g_ed[gw] = make_float2(e1, e3);
    }
}

// ---------- core single-pass agg (reads the given bank) ----------
__device__ __forceinline__ void agg_core(const __half2* __restrict__ lin,
                                         const float2* __restrict__ es,
                                         const float2* __restrict__ edv,
                                         int gw, int lane,
                                         float* accc, float* accr,
                                         float& invc, float& invr) {
    int beg = g_roff[gw], end = g_roff[gw + 1];
    float2 ed = edv[gw];
    int eidx = lane >> 2;
    int cg   = lane & 3;
    float sc = 0.f, sr = 0.f;
    #pragma unroll
    for (int j = 0; j < 8; j++) { accc[j] = 0.f; accr[j] = 0.f; }

    for (int base = beg; base < end; base += 32) {
        int i = base + lane;
        int s_l = 0;
        float wc = 0.f, wr = 0.f;
        if (i < end) {
            s_l = g_csr[i];
            float2 e = es[s_l];
            float ac_ = e.x + ed.x; ac_ = (ac_ > 0.f) ? ac_ : 0.2f * ac_;
            float ar_ = e.y + ed.y; ar_ = (ar_ > 0.f) ? ar_ : 0.2f * ar_;
            wc = __expf(ac_); wr = __expf(ar_);
        }
        sc += wc; sr += wr;

        #pragma unroll
        for (int j = 0; j < 4; j++) {
            if (base + j * 8 >= end) break;             // warp-uniform
            int lsrc = j * 8 + eidx;
            float wcx = __shfl_sync(0xffffffffu, wc, lsrc);
            float wrx = __shfl_sync(0xffffffffu, wr, lsrc);
            int   s   = __shfl_sync(0xffffffffu, s_l, lsrc);
            const __half2* row = lin + (size_t)s * HID + cg * 8;
            const uint4 u0 = *(const uint4*)(row);
            const uint4 u1 = *(const uint4*)(row + 4);
            float2 f0 = __half22float2(*(const __half2*)&u0.x);
            float2 f1 = __half22float2(*(const __half2*)&u0.y);
            float2 f2 = __half22float2(*(const __half2*)&u0.z);
            float2 f3 = __half22float2(*(const __half2*)&u0.w);
            float2 f4 = __half22float2(*(const __half2*)&u1.x);
            float2 f5 = __half22float2(*(const __half2*)&u1.y);
            float2 f6 = __half22float2(*(const __half2*)&u1.z);
            float2 f7 = __half22float2(*(const __half2*)&u1.w);
            accc[0] = fmaf(wcx, f0.x, accc[0]); accr[0] = fmaf(wrx, f0.y, accr[0]);
            accc[1] = fmaf(wcx, f1.x, accc[1]); accr[1] = fmaf(wrx, f1.y, accr[1]);
            accc[2] = fmaf(wcx, f2.x, accc[2]); accr[2] = fmaf(wrx, f2.y, accr[2]);
            accc[3] = fmaf(wcx, f3.x, accc[3]); accr[3] = fmaf(wrx, f3.y, accr[3]);
            accc[4] = fmaf(wcx, f4.x, accc[4]); accr[4] = fmaf(wrx, f4.y, accr[4]);
            accc[5] = fmaf(wcx, f5.x, accc[5]); accr[5] = fmaf(wrx, f5.y, accr[5]);
            accc[6] = fmaf(wcx, f6.x, accc[6]); accr[6] = fmaf(wrx, f6.y, accr[6]);
            accc[7] = fmaf(wcx, f7.x, accc[7]); accr[7] = fmaf(wrx, f7.y, accr[7]);
        }
    }
    #pragma unroll
    for (int o = 16; o; o >>= 1) {
        sc += __shfl_xor_sync(0xffffffffu, sc, o);
        sr += __shfl_xor_sync(0xffffffffu, sr, o);
    }
    invc = 1.0f / sc; invr = 1.0f / sr;
    #pragma unroll
    for (int o = 4; o <= 16; o <<= 1) {
        #pragma unroll
        for (int j = 0; j < 8; j++) {
            accc[j] += __shfl_xor_sync(0xffffffffu, accc[j], o);
            accr[j] += __shfl_xor_sync(0xffffffffu, accr[j], o);
        }
    }
}

// ---- aggA: layer-1 agg + ReLU + layer-2 linear + layer-2 att coeffs ----
__global__ void __launch_bounds__(256) k_aggA(
    const float* __restrict__ b1c, const float* __restrict__ b1r,
    const float* __restrict__ W2c, const float* __restrict__ as2c, const float* __restrict__ ad2c,
    const float* __restrict__ W2r, const float* __restrict__ as2r, const float* __restrict__ ad2r,
    int n) {
    __shared__ float Wsc[HID * HID], Wsr[HID * HID];
    __shared__ float bsh[2 * HID];
    __shared__ float av[4 * HID];
    for (int i = threadIdx.x; i < HID * HID; i += blockDim.x) {
        Wsc[i] = W2c[i]; Wsr[i] = W2r[i];
    }
    if (threadIdx.x < HID) {
        bsh[threadIdx.x]          = b1c[threadIdx.x];
        bsh[HID + threadIdx.x]    = b1r[threadIdx.x];
        av[threadIdx.x]           = as2c[threadIdx.x];
        av[HID + threadIdx.x]     = ad2c[threadIdx.x];
        av[2 * HID + threadIdx.x] = as2r[threadIdx.x];
        av[3 * HID + threadIdx.x] = ad2r[threadIdx.x];
    }
    __syncthreads();
    int gw = (blockIdx.x * blockDim.x + threadIdx.x) >> 5;
    int lane = threadIdx.x & 31;
    if (gw >= n) return;
    int cg = lane & 3;

    float accc[8], accr[8], invc, invr;
    agg_core(g_lin, g_es, g_ed, gw, lane, accc, accr, invc, invr);

    float hc[8], hr[8];
    #pragma unroll
    for (int j = 0; j < 8; j++) {
        hc[j] = fmaxf(fmaf(accc[j], invc, bsh[cg * 8 + j]), 0.f);
        hr[j] = fmaxf(fmaf(accr[j], invr, bsh[HID + cg * 8 + j]), 0.f);
    }
    // layer-2 linear: channel k lives on lane k>>3, register k&7
    float ac = 0.f, ar = 0.f;
    #pragma unroll
    for (int k = 0; k < HID; k++) {
        float tc = __shfl_sync(0xffffffffu, hc[k & 7], k >> 3);
        float tr = __shfl_sync(0xffffffffu, hr[k & 7], k >> 3);
        ac = fmaf(tc, Wsc[k * HID + lane], ac);
        ar = fmaf(tr, Wsr[k * HID + lane], ar);
    }
    g_lin2[(size_t)gw * HID + lane] = __floats2half2_rn(ac, ar);
    float e0 = ac * av[lane], e1 = ac * av[HID + lane];
    float e2 = ar * av[2 * HID + lane], e3 = ar * av[3 * HID + lane];
    #pragma unroll
    for (int o = 16; o; o >>= 1) {
        e0 += __shfl_xor_sync(0xffffffffu, e0, o);
        e1 += __shfl_xor_sync(0xffffffffu, e1, o);
        e2 += __shfl_xor_sync(0xffffffffu, e2, o);
        e3 += __shfl_xor_sync(0xffffffffu, e3, o);
    }
    if (lane == 0) {
        g_es2[gw] = make_float2(e0, e2);
        g_ed2[gw] = make_float2(e1, e3);
    }
}

// ---- aggB: layer-2 agg + ReLU + head GEMMs + sigmoid(c) -> d_out ----
__global__ void __launch_bounds__(256) k_aggB(
    const float* __restrict__ b2c, const float* __restrict__ b2r,
    const float* __restrict__ lWc, const float* __restrict__ lbc,
    const float* __restrict__ lWr, const float* __restrict__ lbr,
    float* __restrict__ out, int n) {
    __shared__ float Wsc[HID * HID], Wsr[HID * HID];
    __shared__ float bsh[2 * HID];
    __shared__ float lbsh[2 * HID];
    for (int i = threadIdx.x; i < HID * HID; i += blockDim.x) {
        Wsc[i] = lWc[i]; Wsr[i] = lWr[i];
    }
    if (threadIdx.x < HID) {
        bsh[threadIdx.x]        = b2c[threadIdx.x];
        bsh[HID + threadIdx.x]  = b2r[threadIdx.x];
        lbsh[threadIdx.x]       = lbc[threadIdx.x];
        lbsh[HID + threadIdx.x] = lbr[threadIdx.x];
    }
    __syncthreads();
    int gw = (blockIdx.x * blockDim.x + threadIdx.x) >> 5;
    int lane = threadIdx.x & 31;
    if (gw >= n) return;
    int cg = lane & 3;

    float accc[8], accr[8], invc, invr;
    agg_core(g_lin2, g_es2, g_ed2, gw, lane, accc, accr, invc, invr);

    float hc[8], hr[8];
    #pragma unroll
    for (int j = 0; j < 8; j++) {
        hc[j] = fmaxf(fmaf(accc[j], invc, bsh[cg * 8 + j]), 0.f);
        hr[j] = fmaxf(fmaf(accr[j], invr, bsh[HID + cg * 8 + j]), 0.f);
    }
    float ac = lbsh[lane], ar = lbsh[HID + lane];
    #pragma unroll
    for (int k = 0; k < HID; k++) {
        float tc = __shfl_sync(0xffffffffu, hc[k & 7], k >> 3);
        float tr = __shfl_sync(0xffffffffu, hr[k & 7], k >> 3);
        ac = fmaf(tc, Wsc[k * HID + lane], ac);
        ar = fmaf(tr, Wsr[k * HID + lane], ar);
    }
    out[(size_t)gw * HID + lane] = 1.0f / (1.0f + __expf(-ac));
    out[(size_t)n * HID + (size_t)gw * HID + lane] = ar;
}

// ---------------- launch ----------------
extern "C" void kernel_launch(void* const* d_in, const int* in_sizes, int n_in,
                              void* d_out, int out_size) {
    const float* x = (const float*)d_in[0];
    int n = in_sizes[0] / 64;

    // params: c at d_in[2..11], r at d_in[12..21]
    const float** c = (const float**)(d_in + 2);
    const float** r = (const float**)(d_in + 12);

    const int T = 256;
    long long nelem = in_sizes[1];
    int nb_scan = (n + 1023) / 1024;
    int nb = (n * 32 + T - 1) / T;  // warp per node

    if (nelem == 2LL * EEMAX) {            // int32 [2, E]
        const int* ei = (const int*)d_in[1];
        int E = EEMAX;
        int nt8 = (E + 7) / 8;
        int nb_hist = (nt8 + T - 1) / T;
        k_front<<<nb + nb_hist, T>>>(x, c[0], c[1], c[2], r[0], r[1], r[2],
                                     ei + E, E, n, nb);
        kb_scan1<<<nb_scan, 1024>>>(n);
        kb_scan23<<<nb_scan, 1024>>>(nb_scan, n);
        k_scatter8<<<nb_hist, T>>>(ei, ei + E, E, n);
    } else {                               // int64 [2, E] fallback
        const long long* ei = (const long long*)d_in[1];
        int E = (int)(nelem / 2);
        k_lin1_only<<<nb, T>>>(x, c[0], c[1], c[2], r[0], r[1], r[2], n);
        k_hist64<<<(E + T - 1) / T, T>>>(ei + E, E, n);
        kb_scan1<<<nb_scan, 1024>>>(n);
        kb_scan23<<<nb_scan, 1024>>>(nb_scan, n);
        k_scatter64<<<(E + T - 1) / T, T>>>(ei, ei + E, E, n);
    }

    k_aggA<<<nb, T>>>(c[3], r[3], c[4], c[5], c[6], r[4], r[5], r[6], n);
    k_aggB<<<nb, T>>>(c[7], r[7], c[8], c[9], r[8], r[9], (float*)d_out, n);
}

// round 13
// speedup vs baseline: 1.9017x; 1.0163x over previous
#include <cuda_runtime.h>
#include <cuda_fp16.h>

#define NN    50000
#define EEMAX 1600000
#define ETOT  (EEMAX + NN)
#define HID   32

// ---- static scratch (module zero-init; g_deg kept zero as an invariant) ----
__device__ int    g_deg[NN];
__device__ int    g_roff[NN + 1];
__device__ int    g_cur[NN];
__device__ int    g_rank[EEMAX];
__device__ int    g_csr[ETOT];
__device__ int    g_part[64];   // lookback flags: 0 = unpublished, else total+1
// bank 1: layer-1 features/scores   bank 2: layer-2 (written by aggA)
__device__ __align__(16) __half2 g_lin[NN * HID];
__device__ __align__(16) __half2 g_lin2[NN * HID];
__device__ __align__(8)  float2 g_es[NN];
__device__ __align__(8)  float2 g_es2[NN];
__device__ __align__(8)  float2 g_ed[NN];
__device__ __align__(8)  float2 g_ed2[NN];

// ---------------- fused front: lin1 blocks + hist blocks ----------------
__global__ void __launch_bounds__(256) k_front(
    const float* __restrict__ x,
    const float* __restrict__ Wc, const float* __restrict__ asc_, const float* __restrict__ adc,
    const float* __restrict__ Wr, const float* __restrict__ asr_, const float* __restrict__ adr,
    const int* __restrict__ dst, int E, int n, int nb_lin) {
    if (blockIdx.x >= (unsigned)nb_lin) {
        // ---- histogram + rank path (keeps atomic return = rank) ----
        int hb = blockIdx.x - nb_lin;
        int base = (hb * blockDim.x + threadIdx.x) * 8;
        if (base + 7 < E) {
            int4 a = *(const int4*)(dst + base);
            int4 b = *(const int4*)(dst + base + 4);
            int d[8] = {a.x, a.y, a.z, a.w, b.x, b.y, b.z, b.w};
            int rk[8];
            #pragma unroll
            for (int k = 0; k < 8; k++) {
                bool ok = (unsigned)d[k] < (unsigned)n;
                rk[k] = ok ? atomicAdd(&g_deg[d[k]], 1) : -1;
            }
            *(int4*)(g_rank + base)     = make_int4(rk[0], rk[1], rk[2], rk[3]);
            *(int4*)(g_rank + base + 4) = make_int4(rk[4], rk[5], rk[6], rk[7]);
        } else {
            for (int k = base; k < E; k++) {
                int dv = dst[k];
                g_rank[k] = ((unsigned)dv < (unsigned)n)
                            ? atomicAdd(&g_deg[dv], 1) : -1;
            }
        }
        return;
    }
    // ---- lin1 path ----
    __shared__ float Wsc[64 * HID], Wsr[64 * HID];
    __shared__ float av[4 * HID];
    for (int i = threadIdx.x; i < 64 * HID; i += blockDim.x) {
        Wsc[i] = Wc[i]; Wsr[i] = Wr[i];
    }
    if (threadIdx.x < HID) {
        av[threadIdx.x]           = asc_[threadIdx.x];
        av[HID + threadIdx.x]     = adc[threadIdx.x];
        av[2 * HID + threadIdx.x] = asr_[threadIdx.x];
        av[3 * HID + threadIdx.x] = adr[threadIdx.x];
    }
    __syncthreads();
    int gw = (blockIdx.x * blockDim.x + threadIdx.x) >> 5;
    int lane = threadIdx.x & 31;
    if (gw >= n) return;
    const float* xr = x + (size_t)gw * 64;
    float ac = 0.f, ar = 0.f;
    #pragma unroll
    for (int k = 0; k < 64; k++) {
        float xv = xr[k];
        ac = fmaf(xv, Wsc[k * HID + lane], ac);
        ar = fmaf(xv, Wsr[k * HID + lane], ar);
    }
    g_lin[(size_t)gw * HID + lane] = __floats2half2_rn(ac, ar);
    float e0 = ac * av[lane], e1 = ac * av[HID + lane];
    float e2 = ar * av[2 * HID + lane], e3 = ar * av[3 * HID + lane];
    #pragma unroll
    for (int o = 16; o; o >>= 1) {
        e0 += __shfl_xor_sync(0xffffffffu, e0, o);
        e1 += __shfl_xor_sync(0xffffffffu, e1, o);
        e2 += __shfl_xor_sync(0xffffffffu, e2, o);
        e3 += __shfl_xor_sync(0xffffffffu, e3, o);
    }
    if (lane == 0) {
        g_es[gw] = make_float2(e0, e2);
        g_ed[gw] = make_float2(e1, e3);
    }
}

__global__ void k_hist64(const long long* __restrict__ dst, int E, int n) {
    int e = blockIdx.x * blockDim.x + threadIdx.x;
    if (e < E) {
        int d = (int)dst[e];
        if ((unsigned)d < (unsigned)n) atomicAdd(&g_deg[d], 1);
    }
}

__device__ __forceinline__ int warp_incl_scan(int x, int lane) {
    #pragma unroll
    for (int o = 1; o < 32; o <<= 1) {
        int y = __shfl_up_sync(0xffffffffu, x, o);
        if (lane >= o) x += y;
    }
    return x;
}

// ---- single-kernel decoupled-lookback scan (replaces scan1 + scan23) ----
// Publishes block total as total+1 (0 = unpublished; totals >= 1024 so
// unambiguous on first zero-init run). Graph replays leave stale values that
// are IDENTICAL to what this run publishes (deterministic) -> benign.
// All 49 blocks co-resident (148 SMs) -> spin is deadlock-free.
__global__ void kb_scan_lb(int nbp, int n) {
    __shared__ int wsum[32];
    __shared__ int s_prev;
    int tid = threadIdx.x, lane = tid & 31, wid = tid >> 5;
    int i = blockIdx.x * 1024 + tid;
    int v = 0;
    if (i < n) { v = g_deg[i] + 1; g_deg[i] = 0; }   // +1 = self loop
    int x = warp_incl_scan(v, lane);
    if (lane == 31) wsum[wid] = x;
    __syncthreads();
    if (wid == 0) wsum[lane] = warp_incl_scan(wsum[lane], lane);
    __syncthreads();
    int incl = x + (wid ? wsum[wid - 1] : 0);
    int blk_total = wsum[31];
    if (tid == 0)
        ((volatile int*)g_part)[blockIdx.x] = blk_total + 1;   // publish
    // lookback (warp 0): sum all predecessors' totals
    if (wid == 0) {
        int sum = 0;
        for (int j = lane; j < blockIdx.x; j += 32) {
            int fv;
            do { fv = ((volatile int*)g_part)[j]; } while (fv == 0);
            sum += fv - 1;
        }
        #pragma unroll
        for (int o = 16; o; o >>= 1) sum += __shfl_xor_sync(0xffffffffu, sum, o);
        if (lane == 0) s_prev = sum;
    }
    __syncthreads();
    int off = s_prev;
    if (i < n) {
        int r = incl - v + off;
        g_roff[i] = r;
        g_csr[r]  = i;        // self loop in first slot
        g_cur[i]  = r + 1;    // (used by int64 fallback scatter only)
    }
    if (blockIdx.x == (unsigned)(nbp - 1) && i == n - 1)
        g_roff[n] = incl + off;
}

// atomic-free scatter: pos = roff[d] + 1 + rank (rank from hist pass)
__global__ void k_scatter8(const int* __restrict__ src,
                           const int* __restrict__ dst, int E, int n) {
    int base = (blockIdx.x * blockDim.x + threadIdx.x) * 8;
    if (base + 7 < E) {
        int4 sa = *(const int4*)(src + base);
        int4 sb = *(const int4*)(src + base + 4);
        int4 da = *(const int4*)(dst + base);
        int4 db = *(const int4*)(dst + base + 4);
        int4 ra = *(const int4*)(g_rank + base);
        int4 rb = *(const int4*)(g_rank + base + 4);
        int s[8] = {sa.x, sa.y, sa.z, sa.w, sb.x, sb.y, sb.z, sb.w};
        int d[8] = {da.x, da.y, da.z, da.w, db.x, db.y, db.z, db.w};
        int rk[8] = {ra.x, ra.y, ra.z, ra.w, rb.x, rb.y, rb.z, rb.w};
        int pos[8];
        #pragma unroll
        for (int k = 0; k < 8; k++)
            pos[k] = (rk[k] >= 0) ? (g_roff[d[k]] + 1 + rk[k]) : -1;
        #pragma unroll
        for (int k = 0; k < 8; k++)
            if (pos[k] >= 0) g_csr[pos[k]] = s[k];
    } else {
        for (int k = base; k < E; k++) {
            int rk = g_rank[k];
            if (rk >= 0) {
                int s = src[k], d = dst[k];
                if ((unsigned)s < (unsigned)n)
                    g_csr[g_roff[d] + 1 + rk] = s;
            }
        }
    }
}

__global__ void k_scatter64(const long long* __restrict__ src,
                            const long long* __restrict__ dst, int E, int n) {
    int e = blockIdx.x * blockDim.x + threadIdx.x;
    if (e >= E) return;
    int s = (int)src[e], d = (int)dst[e];
    if ((unsigned)s >= (unsigned)n || (unsigned)d >= (unsigned)n) return;
    int pos = atomicAdd(&g_cur[d], 1);
    g_csr[pos] = s;
}

// int64 fallback lin1 (separate, unfused)
__global__ void __launch_bounds__(256) k_lin1_only(
    const float* __restrict__ x,
    const float* __restrict__ Wc, const float* __restrict__ asc_, const float* __restrict__ adc,
    const float* __restrict__ Wr, const float* __restrict__ asr_, const float* __restrict__ adr,
    int n) {
    __shared__ float Wsc[64 * HID], Wsr[64 * HID];
    __shared__ float av[4 * HID];
    for (int i = threadIdx.x; i < 64 * HID; i += blockDim.x) {
        Wsc[i] = Wc[i]; Wsr[i] = Wr[i];
    }
    if (threadIdx.x < HID) {
        av[threadIdx.x]           = asc_[threadIdx.x];
        av[HID + threadIdx.x]     = adc[threadIdx.x];
        av[2 * HID + threadIdx.x] = asr_[threadIdx.x];
        av[3 * HID + threadIdx.x] = adr[threadIdx.x];
    }
    __syncthreads();
    int gw = (blockIdx.x * blockDim.x + threadIdx.x) >> 5;
    int lane = threadIdx.x & 31;
    if (gw >= n) return;
    const float* xr = x + (size_t)gw * 64;
    float ac = 0.f, ar = 0.f;
    #pragma unroll
    for (int k = 0; k < 64; k++) {
        float xv = xr[k];
        ac = fmaf(xv, Wsc[k * HID + lane], ac);
        ar = fmaf(xv, Wsr[k * HID + lane], ar);
    }
    g_lin[(size_t)gw * HID + lane] = __floats2half2_rn(ac, ar);
    float e0 = ac * av[lane], e1 = ac * av[HID + lane];
    float e2 = ar * av[2 * HID + lane], e3 = ar * av[3 * HID + lane];
    #pragma unroll
    for (int o = 16; o; o >>= 1) {
        e0 += __shfl_xor_sync(0xffffffffu, e0, o);
        e1 += __shfl_xor_sync(0xffffffffu, e1, o);
        e2 += __shfl_xor_sync(0xffffffffu, e2, o);
        e3 += __shfl_xor_sync(0xffffffffu, e3, o);
    }
    if (lane == 0) {
        g_es[gw] = make_float2(e0, e2);
        g_ed[gw] = make_float2(e1, e3);
    }
}

// ---------- core single-pass agg with csr software pipelining ----------
__device__ __forceinline__ void agg_core(const __half2* __restrict__ lin,
                                         const float2* __restrict__ es,
                                         const float2* __restrict__ edv,
                                         int gw, int lane,
                                         float* accc, float* accr,
                                         float& invc, float& invr) {
    int beg = g_roff[gw], end = g_roff[gw + 1];
    float2 ed = edv[gw];
    int eidx = lane >> 2;
    int cg   = lane & 3;
    float sc = 0.f, sr = 0.f;
    #pragma unroll
    for (int j = 0; j < 8; j++) { accc[j] = 0.f; accr[j] = 0.f; }

    // prefetch first chunk's csr
    int i0 = beg + lane;
    int s_next = (i0 < end) ? g_csr[i0] : 0;

    for (int base = beg; base < end; base += 32) {
        int s_l = s_next;
        // issue es gather for current chunk
        float2 e = es[s_l];
        // prefetch next chunk's csr (overlaps with es gather + FMAs below)
        int inext = base + 32 + lane;
        int s_n2 = 0;
        if (inext < end) s_n2 = g_csr[inext];
        // weights
        float wc = 0.f, wr = 0.f;
        if (base + lane < end) {
            float ac_ = e.x + ed.x; ac_ = (ac_ > 0.f) ? ac_ : 0.2f * ac_;
            float ar_ = e.y + ed.y; ar_ = (ar_ > 0.f) ? ar_ : 0.2f * ar_;
            wc = __expf(ac_); wr = __expf(ar_);
        }
        sc += wc; sr += wr;

        #pragma unroll
        for (int j = 0; j < 4; j++) {
            if (base + j * 8 >= end) break;             // warp-uniform
            int lsrc = j * 8 + eidx;
            float wcx = __shfl_sync(0xffffffffu, wc, lsrc);
            float wrx = __shfl_sync(0xffffffffu, wr, lsrc);
            int   s   = __shfl_sync(0xffffffffu, s_l, lsrc);
            const __half2* row = lin + (size_t)s * HID + cg * 8;
            const uint4 u0 = *(const uint4*)(row);
            const uint4 u1 = *(const uint4*)(row + 4);
            float2 f0 = __half22float2(*(const __half2*)&u0.x);
            float2 f1 = __half22float2(*(const __half2*)&u0.y);
            float2 f2 = __half22float2(*(const __half2*)&u0.z);
            float2 f3 = __half22float2(*(const __half2*)&u0.w);
            float2 f4 = __half22float2(*(const __half2*)&u1.x);
            float2 f5 = __half22float2(*(const __half2*)&u1.y);
            float2 f6 = __half22float2(*(const __half2*)&u1.z);
            float2 f7 = __half22float2(*(const __half2*)&u1.w);
            accc[0] = fmaf(wcx, f0.x, accc[0]); accr[0] = fmaf(wrx, f0.y, accr[0]);
            accc[1] = fmaf(wcx, f1.x, accc[1]); accr[1] = fmaf(wrx, f1.y, accr[1]);
            accc[2] = fmaf(wcx, f2.x, accc[2]); accr[2] = fmaf(wrx, f2.y, accr[2]);
            accc[3] = fmaf(wcx, f3.x, accc[3]); accr[3] = fmaf(wrx, f3.y, accr[3]);
            accc[4] = fmaf(wcx, f4.x, accc[4]); accr[4] = fmaf(wrx, f4.y, accr[4]);
            accc[5] = fmaf(wcx, f5.x, accc[5]); accr[5] = fmaf(wrx, f5.y, accr[5]);
            accc[6] = fmaf(wcx, f6.x, accc[6]); accr[6] = fmaf(wrx, f6.y, accr[6]);
            accc[7] = fmaf(wcx, f7.x, accc[7]); accr[7] = fmaf(wrx, f7.y, accr[7]);
        }
        s_next = s_n2;
    }
    #pragma unroll
    for (int o = 16; o; o >>= 1) {
        sc += __shfl_xor_sync(0xffffffffu, sc, o);
        sr += __shfl_xor_sync(0xffffffffu, sr, o);
    }
    invc = 1.0f / sc; invr = 1.0f / sr;
    #pragma unroll
    for (int o = 4; o <= 16; o <<= 1) {
        #pragma unroll
        for (int j = 0; j < 8; j++) {
            accc[j] += __shfl_xor_sync(0xffffffffu, accc[j], o);
            accr[j] += __shfl_xor_sync(0xffffffffu, accr[j], o);
        }
    }
}

// ---- aggA: layer-1 agg + ReLU + layer-2 linear + layer-2 att coeffs ----
__global__ void __launch_bounds__(256) k_aggA(
    const float* __restrict__ b1c, const float* __restrict__ b1r,
    const float* __restrict__ W2c, const float* __restrict__ as2c, const float* __restrict__ ad2c,
    const float* __restrict__ W2r, const float* __restrict__ as2r, const float* __restrict__ ad2r,
    int n) {
    __shared__ float Wsc[HID * HID], Wsr[HID * HID];
    __shared__ float bsh[2 * HID];
    __shared__ float av[4 * HID];
    for (int i = threadIdx.x; i < HID * HID; i += blockDim.x) {
        Wsc[i] = W2c[i]; Wsr[i] = W2r[i];
    }
    if (threadIdx.x < HID) {
        bsh[threadIdx.x]          = b1c[threadIdx.x];
        bsh[HID + threadIdx.x]    = b1r[threadIdx.x];
        av[threadIdx.x]           = as2c[threadIdx.x];
        av[HID + threadIdx.x]     = ad2c[threadIdx.x];
        av[2 * HID + threadIdx.x] = as2r[threadIdx.x];
        av[3 * HID + threadIdx.x] = ad2r[threadIdx.x];
    }
    __syncthreads();
    int gw = (blockIdx.x * blockDim.x + threadIdx.x) >> 5;
    int lane = threadIdx.x & 31;
    if (gw >= n) return;
    int cg = lane & 3;

    float accc[8], accr[8], invc, invr;
    agg_core(g_lin, g_es, g_ed, gw, lane, accc, accr, invc, invr);

    float hc[8], hr[8];
    #pragma unroll
    for (int j = 0; j < 8; j++) {
        hc[j] = fmaxf(fmaf(accc[j], invc, bsh[cg * 8 + j]), 0.f);
        hr[j] = fmaxf(fmaf(accr[j], invr, bsh[HID + cg * 8 + j]), 0.f);
    }
    // layer-2 linear: channel k lives on lane k>>3, register k&7
    float ac = 0.f, ar = 0.f;
    #pragma unroll
    for (int k = 0; k < HID; k++) {
        float tc = __shfl_sync(0xffffffffu, hc[k & 7], k >> 3);
        float tr = __shfl_sync(0xffffffffu, hr[k & 7], k >> 3);
        ac = fmaf(tc, Wsc[k * HID + lane], ac);
        ar = fmaf(tr, Wsr[k * HID + lane], ar);
    }
    g_lin2[(size_t)gw * HID + lane] = __floats2half2_rn(ac, ar);
    float e0 = ac * av[lane], e1 = ac * av[HID + lane];
    float e2 = ar * av[2 * HID + lane], e3 = ar * av[3 * HID + lane];
    #pragma unroll
    for (int o = 16; o; o >>= 1) {
        e0 += __shfl_xor_sync(0xffffffffu, e0, o);
        e1 += __shfl_xor_sync(0xffffffffu, e1, o);
        e2 += __shfl_xor_sync(0xffffffffu, e2, o);
        e3 += __shfl_xor_sync(0xffffffffu, e3, o);
    }
    if (lane == 0) {
        g_es2[gw] = make_float2(e0, e2);
        g_ed2[gw] = make_float2(e1, e3);
    }
}

// ---- aggB: layer-2 agg + ReLU + head GEMMs + sigmoid(c) -> d_out ----
__global__ void __launch_bounds__(256) k_aggB(
    const float* __restrict__ b2c, const float* __restrict__ b2r,
    const float* __restrict__ lWc, const float* __restrict__ lbc,
    const float* __restrict__ lWr, const float* __restrict__ lbr,
    float* __restrict__ out, int n) {
    __shared__ float Wsc[HID * HID], Wsr[HID * HID];
    __shared__ float bsh[2 * HID];
    __shared__ float lbsh[2 * HID];
    for (int i = threadIdx.x; i < HID * HID; i += blockDim.x) {
        Wsc[i] = lWc[i]; Wsr[i] = lWr[i];
    }
    if (threadIdx.x < HID) {
        bsh[threadIdx.x]        = b2c[threadIdx.x];
        bsh[HID + threadIdx.x]  = b2r[threadIdx.x];
        lbsh[threadIdx.x]       = lbc[threadIdx.x];
        lbsh[HID + threadIdx.x] = lbr[threadIdx.x];
    }
    __syncthreads();
    int gw = (blockIdx.x * blockDim.x + threadIdx.x) >> 5;
    int lane = threadIdx.x & 31;
    if (gw >= n) return;
    int cg = lane & 3;

    float accc[8], accr[8], invc, invr;
    agg_core(g_lin2, g_es2, g_ed2, gw, lane, accc, accr, invc, invr);

    float hc[8], hr[8];
    #pragma unroll
    for (int j = 0; j < 8; j++) {
        hc[j] = fmaxf(fmaf(accc[j], invc, bsh[cg * 8 + j]), 0.f);
        hr[j] = fmaxf(fmaf(accr[j], invr, bsh[HID + cg * 8 + j]), 0.f);
    }
    float ac = lbsh[lane], ar = lbsh[HID + lane];
    #pragma unroll
    for (int k = 0; k < HID; k++) {
        float tc = __shfl_sync(0xffffffffu, hc[k & 7], k >> 3);
        float tr = __shfl_sync(0xffffffffu, hr[k & 7], k >> 3);
        ac = fmaf(tc, Wsc[k * HID + lane], ac);
        ar = fmaf(tr, Wsr[k * HID + lane], ar);
    }
    out[(size_t)gw * HID + lane] = 1.0f / (1.0f + __expf(-ac));
    out[(size_t)n * HID + (size_t)gw * HID + lane] = ar;
}

// ---------------- launch ----------------
extern "C" void kernel_launch(void* const* d_in, const int* in_sizes, int n_in,
                              void* d_out, int out_size) {
    const float* x = (const float*)d_in[0];
    int n = in_sizes[0] / 64;

    // params: c at d_in[2..11], r at d_in[12..21]
    const float** c = (const float**)(d_in + 2);
    const float** r = (const float**)(d_in + 12);

    const int T = 256;
    long long nelem = in_sizes[1];
    int nb_scan = (n + 1023) / 1024;
    int nb = (n * 32 + T - 1) / T;  // warp per node

    if (nelem == 2LL * EEMAX) {            // int32 [2, E]
        const int* ei = (const int*)d_in[1];
        int E = EEMAX;
        int nt8 = (E + 7) / 8;
        int nb_hist = (nt8 + T - 1) / T;
        k_front<<<nb + nb_hist, T>>>(x, c[0], c[1], c[2], r[0], r[1], r[2],
                                     ei + E, E, n, nb);
        kb_scan_lb<<<nb_scan, 1024>>>(nb_scan, n);
        k_scatter8<<<nb_hist, T>>>(ei, ei + E, E, n);
    } else {                               // int64 [2, E] fallback
        const long long* ei = (const long long*)d_in[1];
        int E = (int)(nelem / 2);
        k_lin1_only<<<nb, T>>>(x, c[0], c[1], c[2], r[0], r[1], r[2], n);
        k_hist64<<<(E + T - 1) / T, T>>>(ei + E, E, n);
        kb_scan_lb<<<nb_scan, 1024>>>(nb_scan, n);
        k_scatter64<<<(E + T - 1) / T, T>>>(ei, ei + E, E, n);
    }

    k_aggA<<<nb, T>>>(c[3], r[3], c[4], c[5], c[6], r[4], r[5], r[6], n);
    k_aggB<<<nb, T>>>(c[7], r[7], c[8], c[9], r[8], r[9], (float*)d_out, n);
}